// round 1
// baseline (speedup 1.0000x reference)
#include <cuda_runtime.h>
#include <cuda_bf16.h>

// ---------------------------------------------------------------------------
// INLAttentionBlock: GroupNorm -> QKV -> per-head attention -> 3x INL -> proj+res
// B=8, C=512, H=W=32 (S=1024), nh=8, hd=64
// All activations kept channel-major [b, c, s].
// ---------------------------------------------------------------------------

#define B_ 8
#define C_ 512
#define S_ 1024
#define NH 8
#define HD 64
#define CS (C_ * S_)           // 524288
#define QKV_C (3 * C_)         // 1536

// Scratch (device globals; allocation in kernel_launch is forbidden)
__device__ float g_hgn[(size_t)B_ * CS];                 // 16 MB
__device__ float g_qkv[(size_t)B_ * QKV_C * S_];         // 48 MB
__device__ float g_logits[(size_t)B_ * NH * S_ * S_];    // 256 MB
__device__ float g_h1[(size_t)B_ * CS];                  // 16 MB
__device__ float g_h2[(size_t)B_ * CS];                  // 16 MB
__device__ float g_stats[2 * B_ * NH];                   // mean, rstd per (b,g)

// ---------------------------------------------------------------------------
// GroupNorm: stats (64 blocks) + apply (elementwise)
// ---------------------------------------------------------------------------
__global__ void gn_stats_kernel(const float* __restrict__ x, float* __restrict__ stats) {
    __shared__ float sh[256], sh2[256];
    const int tid = threadIdx.x;
    const float4* p = (const float4*)(x + (size_t)blockIdx.x * 65536);
    float s = 0.f, s2 = 0.f;
    for (int i = tid; i < 16384; i += 256) {
        float4 v = p[i];
        s  += v.x + v.y + v.z + v.w;
        s2 += v.x * v.x + v.y * v.y + v.z * v.z + v.w * v.w;
    }
    sh[tid] = s; sh2[tid] = s2;
    __syncthreads();
    for (int st = 128; st > 0; st >>= 1) {
        if (tid < st) { sh[tid] += sh[tid + st]; sh2[tid] += sh2[tid + st]; }
        __syncthreads();
    }
    if (tid == 0) {
        float mean = sh[0] * (1.f / 65536.f);
        float var  = sh2[0] * (1.f / 65536.f) - mean * mean;
        stats[2 * blockIdx.x]     = mean;
        stats[2 * blockIdx.x + 1] = rsqrtf(var + 1e-5f);
    }
}

__global__ void gn_apply_kernel(const float* __restrict__ x, const float* __restrict__ stats,
                                const float* __restrict__ sc, const float* __restrict__ bi,
                                float* __restrict__ out) {
    size_t i4 = (size_t)blockIdx.x * blockDim.x + threadIdx.x;   // float4 index, 1048576 total
    size_t e  = i4 * 4;
    int bg = (int)(e >> 16);            // 65536 elems per (b,g)
    int c  = (int)((e >> 10) & 511);    // channel
    float mean = stats[2 * bg], rstd = stats[2 * bg + 1];
    float a = rstd * sc[c];
    float b = bi[c] - mean * a;
    float4 v = ((const float4*)x)[i4];
    v.x = v.x * a + b; v.y = v.y * a + b; v.z = v.z * a + b; v.w = v.w * a + b;
    ((float4*)out)[i4] = v;
}

// ---------------------------------------------------------------------------
// Generic tiled SGEMM: out[n*ldO+m] = epi( scale * sum_k A(k,m)*B(k,n) )
//   A(k,m) = AK ? A[m*ldA+k] : A[k*ldA+m]
//   B(k,n) = BKM ? B[n*ldB+k] : B[k*ldB+n]
// EPI: 0 = +bias (if nonnull); 1 = E + 0.1*tanh(val+bias); 2 = E + val + bias
// Block tile 128(M) x 64(N) x 16(K), 256 threads, 8x4 microtile. No bounds
// checks: M % 128 == 0, N % 64 == 0, K % 16 == 0 for all call sites.
// ---------------------------------------------------------------------------
#define TBM 128
#define TBN 64
#define TBK 16

template <int EPI, bool AK, bool BKM>
__global__ __launch_bounds__(256) void gemm_kernel(
    const float* __restrict__ Abase, int ldA, size_t sAo, size_t sAi,
    const float* __restrict__ Bbase, int ldB, size_t sBo, size_t sBi,
    float* __restrict__ Obase, int ldO, size_t sOo, size_t sOi,
    const float* __restrict__ bias,
    const float* __restrict__ Ebase, size_t sEo, size_t sEi,
    int K, int inner, float scale)
{
    __shared__ float As[TBK][TBM + 4];
    __shared__ float Bs[TBK][TBN + 4];

    const int z  = blockIdx.z;
    const int zo = z / inner;
    const int zi = z - zo * inner;
    const float* A = Abase + zo * sAo + zi * sAi;
    const float* B = Bbase + zo * sBo + zi * sBi;
    float*       O = Obase + zo * sOo + zi * sOi;
    const float* E = (EPI != 0) ? (Ebase + zo * sEo + zi * sEi) : nullptr;

    const int m0 = blockIdx.y * TBM;
    const int n0 = blockIdx.x * TBN;
    const int tid = threadIdx.x;
    const int tx = tid & 15;   // n group
    const int ty = tid >> 4;   // m group

    float acc[8][4];
#pragma unroll
    for (int i = 0; i < 8; i++)
#pragma unroll
        for (int j = 0; j < 4; j++) acc[i][j] = 0.f;

    for (int k0 = 0; k0 < K; k0 += TBK) {
        // ---- load A tile (16 x 128) ----
        if (!AK) {
#pragma unroll
            for (int r = 0; r < 2; r++) {
                int li = tid + r * 256;          // 0..511 over (k, m/4)
                int k  = li >> 5;
                int m4 = (li & 31) * 4;
                float4 v = *(const float4*)(A + (size_t)(k0 + k) * ldA + m0 + m4);
                *(float4*)(&As[k][m4]) = v;
            }
        } else {
#pragma unroll
            for (int r = 0; r < 2; r++) {
                int li = tid + r * 256;          // 0..511 over (m, k/4)
                int m  = li >> 2;
                int k4 = (li & 3) * 4;
                float4 v = *(const float4*)(A + (size_t)(m0 + m) * ldA + k0 + k4);
                As[k4 + 0][m] = v.x; As[k4 + 1][m] = v.y;
                As[k4 + 2][m] = v.z; As[k4 + 3][m] = v.w;
            }
        }
        // ---- load B tile (16 x 64) ----
        if (!BKM) {
            int k  = tid >> 4;
            int n4 = (tid & 15) * 4;
            float4 v = *(const float4*)(B + (size_t)(k0 + k) * ldB + n0 + n4);
            *(float4*)(&Bs[k][n4]) = v;
        } else {
            int n  = tid >> 2;
            int k4 = (tid & 3) * 4;
            float4 v = *(const float4*)(B + (size_t)(n0 + n) * ldB + k0 + k4);
            Bs[k4 + 0][n] = v.x; Bs[k4 + 1][n] = v.y;
            Bs[k4 + 2][n] = v.z; Bs[k4 + 3][n] = v.w;
        }
        __syncthreads();

#pragma unroll
        for (int k = 0; k < TBK; k++) {
            float4 a0 = *(const float4*)(&As[k][ty * 8]);
            float4 a1 = *(const float4*)(&As[k][ty * 8 + 4]);
            float4 b0 = *(const float4*)(&Bs[k][tx * 4]);
            float a[8] = {a0.x, a0.y, a0.z, a0.w, a1.x, a1.y, a1.z, a1.w};
            float b[4] = {b0.x, b0.y, b0.z, b0.w};
#pragma unroll
            for (int i = 0; i < 8; i++)
#pragma unroll
                for (int j = 0; j < 4; j++)
                    acc[i][j] = fmaf(a[i], b[j], acc[i][j]);
        }
        __syncthreads();
    }

    // ---- epilogue ----
#pragma unroll
    for (int j = 0; j < 4; j++) {
        int n = n0 + tx * 4 + j;
        float bv = bias ? bias[n] : 0.f;
#pragma unroll
        for (int i = 0; i < 8; i++) {
            int m = m0 + ty * 8 + i;
            size_t idx = (size_t)n * ldO + m;
            float val = acc[i][j] * scale + bv;
            if (EPI == 1)      val = E[idx] + 0.1f * tanhf(val);
            else if (EPI == 2) val = E[idx] + val;
            O[idx] = val;
        }
    }
}

// ---------------------------------------------------------------------------
// Row softmax over 1024 contiguous elements. One warp per row.
// ---------------------------------------------------------------------------
__global__ void softmax_kernel(float* __restrict__ logits) {
    const int lane = threadIdx.x & 31;
    const size_t row = (size_t)blockIdx.x * (blockDim.x >> 5) + (threadIdx.x >> 5);
    float4* p = (float4*)(logits + row * 1024);

    float4 v[8];
    float mx = -3.4e38f;
#pragma unroll
    for (int i = 0; i < 8; i++) {
        v[i] = p[lane + i * 32];
        mx = fmaxf(mx, fmaxf(fmaxf(v[i].x, v[i].y), fmaxf(v[i].z, v[i].w)));
    }
#pragma unroll
    for (int o = 16; o > 0; o >>= 1) mx = fmaxf(mx, __shfl_xor_sync(0xffffffffu, mx, o));

    float s = 0.f;
#pragma unroll
    for (int i = 0; i < 8; i++) {
        v[i].x = __expf(v[i].x - mx); v[i].y = __expf(v[i].y - mx);
        v[i].z = __expf(v[i].z - mx); v[i].w = __expf(v[i].w - mx);
        s += v[i].x + v[i].y + v[i].z + v[i].w;
    }
#pragma unroll
    for (int o = 16; o > 0; o >>= 1) s += __shfl_xor_sync(0xffffffffu, s, o);
    float inv = 1.f / s;
#pragma unroll
    for (int i = 0; i < 8; i++) {
        v[i].x *= inv; v[i].y *= inv; v[i].z *= inv; v[i].w *= inv;
        p[lane + i * 32] = v[i];
    }
}

// ---------------------------------------------------------------------------
// Host launcher
// ---------------------------------------------------------------------------
extern "C" void kernel_launch(void* const* d_in, const int* in_sizes, int n_in,
                              void* d_out, int out_size) {
    const float* x        = (const float*)d_in[0];
    const float* gn_scale = (const float*)d_in[1];
    const float* gn_bias  = (const float*)d_in[2];
    const float* qkv_w    = (const float*)d_in[3];
    const float* qkv_b    = (const float*)d_in[4];
    const float* proj_w   = (const float*)d_in[5];
    const float* proj_b   = (const float*)d_in[6];
    const float* inl_w    = (const float*)d_in[7];
    const float* inl_b    = (const float*)d_in[8];
    float* out = (float*)d_out;

    float *hgn, *qkv, *logits, *h1, *h2, *stats;
    cudaGetSymbolAddress((void**)&hgn,    g_hgn);
    cudaGetSymbolAddress((void**)&qkv,    g_qkv);
    cudaGetSymbolAddress((void**)&logits, g_logits);
    cudaGetSymbolAddress((void**)&h1,     g_h1);
    cudaGetSymbolAddress((void**)&h2,     g_h2);
    cudaGetSymbolAddress((void**)&stats,  g_stats);

    const size_t CSz = (size_t)CS;            // 524288
    const size_t QCS = (size_t)QKV_C * S_;    // 1572864
    const size_t SS  = (size_t)S_ * S_;       // 1048576

    // 1) GroupNorm
    gn_stats_kernel<<<B_ * NH, 256>>>(x, stats);
    gn_apply_kernel<<<4096, 256>>>(x, stats, gn_scale, gn_bias, hgn);

    // 2) QKV: qkv[b, o, s] = sum_c W[o,c] * hgn[b,c,s] + qkv_b[o]
    gemm_kernel<0, false, true><<<dim3(QKV_C / TBN, S_ / TBM, B_), 256>>>(
        hgn, S_, CSz, 0,
        qkv_w, C_, 0, 0,
        qkv, S_, QCS, 0,
        qkv_b, nullptr, 0, 0,
        C_, 1, 1.f);

    // 3) QK^T: logits[(b,n)][s, t] = 0.125 * sum_d K[d,t] * Q[d,s]
    //    (m = t from K-matrix, n = s from Q-matrix -> row-contiguous in t)
    gemm_kernel<0, false, false><<<dim3(S_ / TBN, S_ / TBM, B_ * NH), 256>>>(
        qkv + (size_t)C_ * S_, S_, QCS, (size_t)HD * S_,   // K part
        qkv,                   S_, QCS, (size_t)HD * S_,   // Q part
        logits, S_, (size_t)NH * SS, SS,
        nullptr, nullptr, 0, 0,
        HD, NH, 0.125f);

    // 4) softmax over t (contiguous rows)
    softmax_kernel<<<(B_ * NH * S_) / 4, 128>>>(logits);

    // 5) AV: h1[b, n*64+d, s] = sum_t attn[s,t] * V[d,t]
    gemm_kernel<0, true, true><<<dim3(HD / TBN, S_ / TBM, B_ * NH), 256>>>(
        logits, S_, (size_t)NH * SS, SS,                    // attn (m=s, k=t)
        qkv + (size_t)2 * C_ * S_, S_, QCS, (size_t)HD * S_, // V (n=d, k=t)
        h1, S_, CSz, (size_t)HD * S_,
        nullptr, nullptr, 0, 0,
        S_, NH, 1.f);

    // 6) INL refinement x3 (ping-pong h1 <-> h2)
    const float* src = h1;
    float* dst = h2;
    for (int it = 0; it < 3; it++) {
        gemm_kernel<1, false, true><<<dim3(C_ / TBN, S_ / TBM, B_), 256>>>(
            src, S_, CSz, 0,
            inl_w, C_, 0, 0,
            dst, S_, CSz, 0,
            inl_b, src, CSz, 0,
            C_, 1, 1.f);
        const float* t = src; src = dst; dst = (float*)t;
    }
    // after 3 iters result is in h2 (h1->h2->h1->h2), i.e. current `src`

    // 7) proj + residual: out = x + proj_w @ h + proj_b
    gemm_kernel<2, false, true><<<dim3(C_ / TBN, S_ / TBM, B_), 256>>>(
        src, S_, CSz, 0,
        proj_w, C_, 0, 0,
        out, S_, CSz, 0,
        proj_b, x, CSz, 0,
        C_, 1, 1.f);
}

// round 3
// speedup vs baseline: 2.5541x; 2.5541x over previous
#include <cuda_runtime.h>
#include <cstdint>
#include <cstddef>

// ===========================================================================
// INLAttentionBlock via mma.sync tf32 (sm_103-safe PTX):
// GN+T -> QKV -> QK -> softmax -> AV -> 3x INL -> proj+res
// B=8, C=512, S=1024, nh=8, hd=64. Activations token-major [b, s, c].
// ===========================================================================

#define B_ 8
#define C_ 512
#define S_ 1024
#define NH 8
#define CS (C_ * S_)            // 524288

__device__ float g_hgn[(size_t)B_ * S_ * C_];          // [b, s, c]
__device__ float g_qkvT[(size_t)B_ * S_ * 3 * C_];     // [b, s, 3C]
__device__ float g_vt[(size_t)B_ * C_ * S_];           // [b, dglob, t]
__device__ float g_logits[(size_t)B_ * NH * S_ * S_];  // [(b,h), s, t]
__device__ float g_h1[(size_t)B_ * S_ * C_];           // [b, s, c]
__device__ float g_h2[(size_t)B_ * S_ * C_];
__device__ float g_stats[2 * B_ * NH];

// ---------------------------------------------------------------------------
// helpers
// ---------------------------------------------------------------------------
__device__ __forceinline__ uint32_t smem_u32(const void* p) {
    uint32_t a;
    asm("{ .reg .u64 t; cvta.to.shared.u64 t, %1; cvt.u32.u64 %0, t; }" : "=r"(a) : "l"(p));
    return a;
}
__device__ __forceinline__ float rtf32(float x) {
    asm("cvt.rna.tf32.f32 %0, %0;" : "+f"(x));
    return x;
}
__device__ __forceinline__ void ldsm4(uint32_t* r, uint32_t addr) {
    asm volatile("ldmatrix.sync.aligned.m8n8.x4.shared.b16 {%0,%1,%2,%3}, [%4];"
                 : "=r"(r[0]), "=r"(r[1]), "=r"(r[2]), "=r"(r[3]) : "r"(addr));
}
__device__ __forceinline__ void ldsm2(uint32_t* r, uint32_t addr) {
    asm volatile("ldmatrix.sync.aligned.m8n8.x2.shared.b16 {%0,%1}, [%2];"
                 : "=r"(r[0]), "=r"(r[1]) : "r"(addr));
}
__device__ __forceinline__ void mma_tf32(float* d, const uint32_t* a, const uint32_t* b) {
    asm volatile("mma.sync.aligned.m16n8k8.row.col.f32.tf32.tf32.f32 "
                 "{%0,%1,%2,%3}, {%4,%5,%6,%7}, {%8,%9}, {%0,%1,%2,%3};"
                 : "+f"(d[0]), "+f"(d[1]), "+f"(d[2]), "+f"(d[3])
                 : "r"(a[0]), "r"(a[1]), "r"(a[2]), "r"(a[3]), "r"(b[0]), "r"(b[1]));
}

// ---------------------------------------------------------------------------
// GroupNorm stats + fused apply-and-transpose ([c,s] -> [s,c])
// ---------------------------------------------------------------------------
__global__ void gn_stats_kernel(const float* __restrict__ x, float* __restrict__ stats) {
    __shared__ float sh[256], sh2[256];
    const int tid = threadIdx.x;
    const float4* p = (const float4*)(x + (size_t)blockIdx.x * 65536);
    float s = 0.f, s2 = 0.f;
    for (int i = tid; i < 16384; i += 256) {
        float4 v = p[i];
        s  += v.x + v.y + v.z + v.w;
        s2 += v.x * v.x + v.y * v.y + v.z * v.z + v.w * v.w;
    }
    sh[tid] = s; sh2[tid] = s2;
    __syncthreads();
    for (int st = 128; st > 0; st >>= 1) {
        if (tid < st) { sh[tid] += sh[tid + st]; sh2[tid] += sh2[tid + st]; }
        __syncthreads();
    }
    if (tid == 0) {
        float mean = sh[0] * (1.f / 65536.f);
        float var  = sh2[0] * (1.f / 65536.f) - mean * mean;
        stats[2 * blockIdx.x]     = mean;
        stats[2 * blockIdx.x + 1] = rsqrtf(var + 1e-5f);
    }
}

__global__ void gn_apply_t_kernel(const float* __restrict__ x, const float* __restrict__ stats,
                                  const float* __restrict__ sc, const float* __restrict__ bi,
                                  float* __restrict__ hgn) {
    __shared__ float t[32][33];
    const int b = blockIdx.z;
    const int c0 = blockIdx.y * 32;
    const int s0 = blockIdx.x * 32;
    const int tx = threadIdx.x, ty = threadIdx.y;
#pragma unroll
    for (int r = 0; r < 4; r++) {
        int c = c0 + ty + r * 8;
        int bg = b * 8 + (c >> 6);
        float mean = stats[2 * bg], rstd = stats[2 * bg + 1];
        float a = rstd * sc[c];
        float bb = bi[c] - mean * a;
        t[ty + r * 8][tx] = x[(size_t)b * CS + (size_t)c * S_ + s0 + tx] * a + bb;
    }
    __syncthreads();
#pragma unroll
    for (int r = 0; r < 4; r++) {
        int s = s0 + ty + r * 8;
        hgn[(size_t)b * CS + (size_t)s * C_ + c0 + tx] = t[tx][ty + r * 8];
    }
}

// V part of qkvT ([s,o] cols 1024..1535) -> Vt [dglob, t]
__global__ void vt_transpose_kernel(const float* __restrict__ qkvT, float* __restrict__ vt) {
    __shared__ float t[32][33];
    const int b = blockIdx.z;
    const int d0 = blockIdx.y * 32;
    const int t0 = blockIdx.x * 32;
    const int tx = threadIdx.x, ty = threadIdx.y;
#pragma unroll
    for (int r = 0; r < 4; r++) {
        int tt = t0 + ty + r * 8;
        t[ty + r * 8][tx] = qkvT[(size_t)b * S_ * 1536 + (size_t)tt * 1536 + 1024 + d0 + tx];
    }
    __syncthreads();
#pragma unroll
    for (int r = 0; r < 4; r++) {
        int d = d0 + ty + r * 8;
        vt[(size_t)b * CS + (size_t)d * S_ + t0 + tx] = t[tx][ty + r * 8];
    }
}

// ---------------------------------------------------------------------------
// Row softmax (1024 contiguous elems, one warp/row)
// ---------------------------------------------------------------------------
__global__ void softmax_kernel(float* __restrict__ logits) {
    const int lane = threadIdx.x & 31;
    const size_t row = (size_t)blockIdx.x * (blockDim.x >> 5) + (threadIdx.x >> 5);
    float4* p = (float4*)(logits + row * 1024);
    float4 v[8];
    float mx = -3.4e38f;
#pragma unroll
    for (int i = 0; i < 8; i++) {
        v[i] = p[lane + i * 32];
        mx = fmaxf(mx, fmaxf(fmaxf(v[i].x, v[i].y), fmaxf(v[i].z, v[i].w)));
    }
#pragma unroll
    for (int o = 16; o > 0; o >>= 1) mx = fmaxf(mx, __shfl_xor_sync(0xffffffffu, mx, o));
    float s = 0.f;
#pragma unroll
    for (int i = 0; i < 8; i++) {
        v[i].x = __expf(v[i].x - mx); v[i].y = __expf(v[i].y - mx);
        v[i].z = __expf(v[i].z - mx); v[i].w = __expf(v[i].w - mx);
        s += v[i].x + v[i].y + v[i].z + v[i].w;
    }
#pragma unroll
    for (int o = 16; o > 0; o >>= 1) s += __shfl_xor_sync(0xffffffffu, s, o);
    float inv = 1.f / s;
#pragma unroll
    for (int i = 0; i < 8; i++) {
        v[i].x *= inv; v[i].y *= inv; v[i].z *= inv; v[i].w *= inv;
        p[lane + i * 32] = v[i];
    }
}

// ---------------------------------------------------------------------------
// mma.sync tf32 GEMM:  D[m,n] = epi( scale * sum_k A[m,k]*B[n,k] )
// A: [M,K] K-contig (ldA), B: [N,K] K-contig (ldB). BM=128, BN=128/64, BK=32.
// EPI: 0 plain (O[n*ldO+m]); 1 INL tanh; 2 residual; 3 transposed O[m*ldO+n]
// BIAS_MODE: 0 none, 1 bias[m], 2 bias[n]
// ---------------------------------------------------------------------------
template <int BN, int EPI, int BIAS_MODE>
__global__ void __launch_bounds__(256) mm_kernel(
    const float* __restrict__ Abase, int ldA, size_t sAo, size_t sAi,
    const float* __restrict__ Bbase, int ldB, size_t sBo, size_t sBi,
    float* __restrict__ Obase, int ldO, size_t sOo, size_t sOi,
    const float* __restrict__ bias,
    const float* __restrict__ Ebase, size_t sEo, size_t sEi,
    int K, int inner, float scale)
{
    constexpr int ABYTES = 128 * 128;         // 128 rows x 32 f32
    constexpr int BBYTES = BN * 128;
    constexpr int STAGE  = ABYTES + BBYTES;
    constexpr int BF4    = BN / 32;           // B float4 loads/thread/tile
    constexpr int WARPS_M = (BN == 128) ? 2 : 4;
    constexpr int MT = 128 / WARPS_M / 16;    // m16 tiles per warp (4 or 2)
    constexpr int PITCH = (EPI == 3) ? (BN + 4) : 132;

    extern __shared__ char smemc[];
    const uint32_t sb = smem_u32(smemc);
    const int tid = threadIdx.x;
    const int wid = tid >> 5;
    const int lane = tid & 31;
    const int grp = lane >> 2, tig = lane & 3;

    const int z = blockIdx.z;
    const int zo = z / inner;
    const int zi = z - zo * inner;
    const float* Ag = Abase + zo * sAo + zi * sAi;
    const float* Bg = Bbase + zo * sBo + zi * sBi;
    float*       O  = Obase + zo * sOo + zi * sOi;
    const float* E  = (EPI == 1 || EPI == 2) ? (Ebase + zo * sEo + zi * sEi) : nullptr;

    const int m0 = blockIdx.y * 128;
    const int n0 = blockIdx.x * BN;

    const int wm0 = (BN == 128) ? (wid & 1) * 64 : (wid & 3) * 32;
    const int wn0 = (BN == 128) ? (wid >> 1) * 32 : (wid >> 2) * 32;

    // ---- staging address precompute (global + swizzled smem offsets) ----
    const float* aptr[4];
    uint32_t asw[4];
#pragma unroll
    for (int r = 0; r < 4; r++) {
        int li = tid + r * 256;
        int row = li >> 3, k4 = li & 7;
        aptr[r] = Ag + (size_t)(m0 + row) * ldA + k4 * 4;
        asw[r] = (uint32_t)(row * 128 + k4 * 16) ^ ((uint32_t)(row & 7) << 4);
    }
    const float* bptr[BF4];
    uint32_t bsw[BF4];
#pragma unroll
    for (int r = 0; r < BF4; r++) {
        int li = tid + r * 256;
        int row = li >> 3, k4 = li & 7;
        bptr[r] = Bg + (size_t)(n0 + row) * ldB + k4 * 4;
        bsw[r] = (uint32_t)(row * 128 + k4 * 16) ^ ((uint32_t)(row & 7) << 4);
    }

    // ---- ldmatrix per-thread geometry ----
    const int rowA = (lane & 7) + ((lane >> 3) & 1) * 8;
    const uint32_t kxA = ((uint32_t)(lane >> 4)) * 16;
    const int rowB = lane & 7;
    const uint32_t kxB = ((uint32_t)((lane >> 3) & 1)) * 16;
    const uint32_t swz = ((uint32_t)(lane & 7)) << 4;

    float acc[MT][4][4];
#pragma unroll
    for (int mt = 0; mt < MT; mt++)
#pragma unroll
        for (int nt = 0; nt < 4; nt++)
#pragma unroll
            for (int r = 0; r < 4; r++) acc[mt][nt][r] = 0.f;

    const int nkt = K >> 5;

    // prologue: stage tile 0
    {
#pragma unroll
        for (int r = 0; r < 4; r++) {
            float4 v = *(const float4*)(aptr[r]);
            v.x = rtf32(v.x); v.y = rtf32(v.y); v.z = rtf32(v.z); v.w = rtf32(v.w);
            *(float4*)(smemc + asw[r]) = v;
        }
#pragma unroll
        for (int r = 0; r < BF4; r++) {
            float4 v = *(const float4*)(bptr[r]);
            v.x = rtf32(v.x); v.y = rtf32(v.y); v.z = rtf32(v.z); v.w = rtf32(v.w);
            *(float4*)(smemc + ABYTES + bsw[r]) = v;
        }
    }
    __syncthreads();

    for (int kt = 0; kt < nkt; kt++) {
        const int cur = kt & 1;
        const uint32_t As = sb + cur * STAGE;
        const uint32_t Bs = As + ABYTES;

        // prefetch next tile into regs
        float4 pa[4], pb[BF4];
        if (kt + 1 < nkt) {
            const int k0 = (kt + 1) << 5;
#pragma unroll
            for (int r = 0; r < 4; r++) pa[r] = *(const float4*)(aptr[r] + k0);
#pragma unroll
            for (int r = 0; r < BF4; r++) pb[r] = *(const float4*)(bptr[r] + k0);
        }

        // compute on current tile
#pragma unroll
        for (int ks = 0; ks < 4; ks++) {
            uint32_t afr[MT][4];
#pragma unroll
            for (int mt = 0; mt < MT; mt++) {
                uint32_t ad = As + (uint32_t)((wm0 + mt * 16 + rowA) * 128) + (((uint32_t)(ks * 32) + kxA) ^ swz);
                ldsm4(afr[mt], ad);
            }
            uint32_t bfr[4][2];
#pragma unroll
            for (int nt = 0; nt < 4; nt++) {
                uint32_t bd = Bs + (uint32_t)((wn0 + nt * 8 + rowB) * 128) + (((uint32_t)(ks * 32) + kxB) ^ swz);
                ldsm2(bfr[nt], bd);
            }
#pragma unroll
            for (int mt = 0; mt < MT; mt++)
#pragma unroll
                for (int nt = 0; nt < 4; nt++)
                    mma_tf32(acc[mt][nt], afr[mt], bfr[nt]);
        }

        // stage next tile
        if (kt + 1 < nkt) {
            char* As2 = smemc + (cur ^ 1) * STAGE;
#pragma unroll
            for (int r = 0; r < 4; r++) {
                float4 v = pa[r];
                v.x = rtf32(v.x); v.y = rtf32(v.y); v.z = rtf32(v.z); v.w = rtf32(v.w);
                *(float4*)(As2 + asw[r]) = v;
            }
#pragma unroll
            for (int r = 0; r < BF4; r++) {
                float4 v = pb[r];
                v.x = rtf32(v.x); v.y = rtf32(v.y); v.z = rtf32(v.z); v.w = rtf32(v.w);
                *(float4*)(As2 + ABYTES + bsw[r]) = v;
            }
            __syncthreads();
        }
    }

    // ---- epilogue via SMEM transpose buffer ----
    __syncthreads();
    float* Csm = (float*)smemc;

#pragma unroll
    for (int mt = 0; mt < MT; mt++) {
#pragma unroll
        for (int nt = 0; nt < 4; nt++) {
            int m = wm0 + mt * 16 + grp;
            int n = wn0 + nt * 8 + tig * 2;
            if (EPI == 3) {
                Csm[(m)     * PITCH + n]     = acc[mt][nt][0];
                Csm[(m)     * PITCH + n + 1] = acc[mt][nt][1];
                Csm[(m + 8) * PITCH + n]     = acc[mt][nt][2];
                Csm[(m + 8) * PITCH + n + 1] = acc[mt][nt][3];
            } else {
                Csm[(n)     * PITCH + m]     = acc[mt][nt][0];
                Csm[(n + 1) * PITCH + m]     = acc[mt][nt][1];
                Csm[(n)     * PITCH + m + 8] = acc[mt][nt][2];
                Csm[(n + 1) * PITCH + m + 8] = acc[mt][nt][3];
            }
        }
    }
    __syncthreads();

    if (EPI == 3) {
        // store O[(m0+i)*ldO + n0 + j], j contiguous
        constexpr int J4 = BN / 4;
#pragma unroll
        for (int it = 0; it < 128 * J4 / 256; it++) {
            int li = tid + it * 256;
            int i = li / J4, j4 = (li % J4) * 4;
            float4 c = *(float4*)(Csm + i * PITCH + j4);
            c.x *= scale; c.y *= scale; c.z *= scale; c.w *= scale;
            *(float4*)(O + (size_t)(m0 + i) * ldO + n0 + j4) = c;
        }
    } else {
#pragma unroll
        for (int it = 0; it < BN / 8; it++) {
            int li = tid + it * 256;
            int n = li >> 5, m4 = (li & 31) << 2;
            float4 c = *(float4*)(Csm + n * PITCH + m4);
            c.x *= scale; c.y *= scale; c.z *= scale; c.w *= scale;
            if (BIAS_MODE == 1) {
                float4 bm = *(const float4*)(bias + m0 + m4);
                c.x += bm.x; c.y += bm.y; c.z += bm.z; c.w += bm.w;
            } else if (BIAS_MODE == 2) {
                float bn = bias[n0 + n];
                c.x += bn; c.y += bn; c.z += bn; c.w += bn;
            }
            size_t idx = (size_t)(n0 + n) * ldO + m0 + m4;
            if (EPI == 1) {
                float4 e = *(const float4*)(E + idx);
                c.x = e.x + 0.1f * tanhf(c.x); c.y = e.y + 0.1f * tanhf(c.y);
                c.z = e.z + 0.1f * tanhf(c.z); c.w = e.w + 0.1f * tanhf(c.w);
            } else if (EPI == 2) {
                float4 e = *(const float4*)(E + idx);
                c.x += e.x; c.y += e.y; c.z += e.z; c.w += e.w;
            }
            *(float4*)(O + idx) = c;
        }
    }
}

// ---------------------------------------------------------------------------
// Host launcher
// ---------------------------------------------------------------------------
extern "C" void kernel_launch(void* const* d_in, const int* in_sizes, int n_in,
                              void* d_out, int out_size) {
    const float* x        = (const float*)d_in[0];
    const float* gn_scale = (const float*)d_in[1];
    const float* gn_bias  = (const float*)d_in[2];
    const float* qkv_w    = (const float*)d_in[3];
    const float* qkv_b    = (const float*)d_in[4];
    const float* proj_w   = (const float*)d_in[5];
    const float* proj_b   = (const float*)d_in[6];
    const float* inl_w    = (const float*)d_in[7];
    const float* inl_b    = (const float*)d_in[8];
    float* out = (float*)d_out;

    float *hgn, *qkvT, *vt, *logits, *h1, *h2, *stats;
    cudaGetSymbolAddress((void**)&hgn,    g_hgn);
    cudaGetSymbolAddress((void**)&qkvT,   g_qkvT);
    cudaGetSymbolAddress((void**)&vt,     g_vt);
    cudaGetSymbolAddress((void**)&logits, g_logits);
    cudaGetSymbolAddress((void**)&h1,     g_h1);
    cudaGetSymbolAddress((void**)&h2,     g_h2);
    cudaGetSymbolAddress((void**)&stats,  g_stats);

    const int SM128 = 132 * 128 * 4;                    // 67584 (>= 2*STAGE=65536)
    const int SM64  = 2 * (128 + 64) * 32 * 4;          // 49152 (>= epi 34816)
    cudaFuncSetAttribute(mm_kernel<128, 0, 1>, cudaFuncAttributeMaxDynamicSharedMemorySize, SM128);
    cudaFuncSetAttribute(mm_kernel<128, 0, 0>, cudaFuncAttributeMaxDynamicSharedMemorySize, SM128);
    cudaFuncSetAttribute(mm_kernel<64, 3, 0>,  cudaFuncAttributeMaxDynamicSharedMemorySize, SM64);
    cudaFuncSetAttribute(mm_kernel<128, 1, 1>, cudaFuncAttributeMaxDynamicSharedMemorySize, SM128);
    cudaFuncSetAttribute(mm_kernel<128, 2, 2>, cudaFuncAttributeMaxDynamicSharedMemorySize, SM128);

    const size_t CSz = (size_t)CS;
    const size_t SS  = (size_t)S_ * S_;

    // 1) GroupNorm (stats) + apply-with-transpose -> hgn [b, s, c]
    gn_stats_kernel<<<B_ * NH, 256>>>(x, stats);
    gn_apply_t_kernel<<<dim3(32, 16, B_), dim3(32, 8)>>>(x, stats, gn_scale, gn_bias, hgn);

    // 2) QKV: qkvT[s, o] = qkv_w[o,:].hgn[s,:] + qkv_b[o]   (M=o=1536, N=s, K=c)
    mm_kernel<128, 0, 1><<<dim3(8, 12, B_), 256, SM128>>>(
        qkv_w, C_, 0, 0,
        hgn, C_, CSz, 0,
        qkvT, 1536, (size_t)S_ * 1536, 0,
        qkv_b, nullptr, 0, 0,
        C_, 1, 1.f);

    // 3) Vt: V part of qkvT -> [dglob, t]
    vt_transpose_kernel<<<dim3(32, 16, B_), dim3(32, 8)>>>(qkvT, vt);

    // 4) QK^T: logits[(b,h)][s][t] = 0.125 * K[t,:].Q[s,:]   (M=t, N=s, K=d=64)
    mm_kernel<128, 0, 0><<<dim3(8, 8, B_ * NH), 256, SM128>>>(
        qkvT + 512, 1536, (size_t)S_ * 1536, 64,
        qkvT,       1536, (size_t)S_ * 1536, 64,
        logits, S_, (size_t)NH * SS, SS,
        nullptr, nullptr, 0, 0,
        64, NH, 0.125f);

    // 5) softmax over t
    softmax_kernel<<<(B_ * NH * S_) / 4, 128>>>(logits);

    // 6) AV: h1[s][64h+d] = attn[s,:].Vt[d,:]  (M=s, N=d=64, K=t, EPI3)
    mm_kernel<64, 3, 0><<<dim3(1, 8, B_ * NH), 256, SM64>>>(
        logits, S_, (size_t)NH * SS, SS,
        vt, S_, CSz, (size_t)64 * S_,
        h1, C_, CSz, 64,
        nullptr, nullptr, 0, 0,
        S_, NH, 1.f);

    // 7) INL x3: dst[s][o] = src[s][o] + 0.1*tanh(inl_w[o,:].src[s,:] + inl_b[o])
    const float* src = h1;
    float* dst = h2;
    for (int it = 0; it < 3; it++) {
        mm_kernel<128, 1, 1><<<dim3(8, 4, B_), 256, SM128>>>(
            inl_w, C_, 0, 0,
            src, C_, CSz, 0,
            dst, C_, CSz, 0,
            inl_b, src, CSz, 0,
            C_, 1, 1.f);
        const float* t = src; src = dst; dst = (float*)t;
    }

    // 8) proj + residual: out[o][s] = x[o][s] + proj_w[o,:].src[s,:] + proj_b[o]
    //    (M=s, N=o, bias over n)
    mm_kernel<128, 2, 2><<<dim3(4, 8, B_), 256, SM128>>>(
        src, C_, CSz, 0,
        proj_w, C_, 0, 0,
        out, S_, CSz, 0,
        proj_b, x, CSz, 0,
        C_, 1, 1.f);
}

// round 4
// speedup vs baseline: 3.5160x; 1.3766x over previous
#include <cuda_runtime.h>
#include <cstdint>
#include <cstddef>

// ===========================================================================
// INLAttentionBlock via mma.sync tf32 (sm_103-safe PTX):
// GN+T -> QKV -> [flash: QK+softmax+AV fused] -> 3x INL -> proj+res
// B=8, C=512, S=1024, nh=8, hd=64. Activations token-major [b, s, c].
// ===========================================================================

#define B_ 8
#define C_ 512
#define S_ 1024
#define NH 8
#define CS (C_ * S_)            // 524288
#define CEXP 0.18033688011112042f   // 0.125 * log2(e)

__device__ float g_hgn[(size_t)B_ * S_ * C_];          // [b, s, c]
__device__ float g_qkvT[(size_t)B_ * S_ * 3 * C_];     // [b, s, 3C]
__device__ float g_vt[(size_t)B_ * C_ * S_];           // [b, dglob, t]
__device__ float g_h1[(size_t)B_ * S_ * C_];           // [b, s, c]
__device__ float g_h2[(size_t)B_ * S_ * C_];
__device__ float g_stats[2 * B_ * NH];

// ---------------------------------------------------------------------------
// helpers
// ---------------------------------------------------------------------------
__device__ __forceinline__ uint32_t smem_u32(const void* p) {
    uint32_t a;
    asm("{ .reg .u64 t; cvta.to.shared.u64 t, %1; cvt.u32.u64 %0, t; }" : "=r"(a) : "l"(p));
    return a;
}
__device__ __forceinline__ float rtf32(float x) {
    asm("cvt.rna.tf32.f32 %0, %0;" : "+f"(x));
    return x;
}
__device__ __forceinline__ void ldsm4(uint32_t* r, uint32_t addr) {
    asm volatile("ldmatrix.sync.aligned.m8n8.x4.shared.b16 {%0,%1,%2,%3}, [%4];"
                 : "=r"(r[0]), "=r"(r[1]), "=r"(r[2]), "=r"(r[3]) : "r"(addr));
}
__device__ __forceinline__ void ldsm2(uint32_t* r, uint32_t addr) {
    asm volatile("ldmatrix.sync.aligned.m8n8.x2.shared.b16 {%0,%1}, [%2];"
                 : "=r"(r[0]), "=r"(r[1]) : "r"(addr));
}
__device__ __forceinline__ void mma_tf32(float* d, const uint32_t* a, const uint32_t* b) {
    asm volatile("mma.sync.aligned.m16n8k8.row.col.f32.tf32.tf32.f32 "
                 "{%0,%1,%2,%3}, {%4,%5,%6,%7}, {%8,%9}, {%0,%1,%2,%3};"
                 : "+f"(d[0]), "+f"(d[1]), "+f"(d[2]), "+f"(d[3])
                 : "r"(a[0]), "r"(a[1]), "r"(a[2]), "r"(a[3]), "r"(b[0]), "r"(b[1]));
}
#define CP16(sa, ga) asm volatile("cp.async.cg.shared.global [%0], [%1], 16;" :: "r"(sa), "l"((const void*)(ga)))
#define CPCOMMIT()   asm volatile("cp.async.commit_group;" ::: "memory")
#define CPWAIT0()    asm volatile("cp.async.wait_group 0;" ::: "memory")

// ---------------------------------------------------------------------------
// GroupNorm stats + fused apply-and-transpose ([c,s] -> [s,c])
// ---------------------------------------------------------------------------
__global__ void gn_stats_kernel(const float* __restrict__ x, float* __restrict__ stats) {
    __shared__ float sh[256], sh2[256];
    const int tid = threadIdx.x;
    const float4* p = (const float4*)(x + (size_t)blockIdx.x * 65536);
    float s = 0.f, s2 = 0.f;
    for (int i = tid; i < 16384; i += 256) {
        float4 v = p[i];
        s  += v.x + v.y + v.z + v.w;
        s2 += v.x * v.x + v.y * v.y + v.z * v.z + v.w * v.w;
    }
    sh[tid] = s; sh2[tid] = s2;
    __syncthreads();
    for (int st = 128; st > 0; st >>= 1) {
        if (tid < st) { sh[tid] += sh[tid + st]; sh2[tid] += sh2[tid + st]; }
        __syncthreads();
    }
    if (tid == 0) {
        float mean = sh[0] * (1.f / 65536.f);
        float var  = sh2[0] * (1.f / 65536.f) - mean * mean;
        stats[2 * blockIdx.x]     = mean;
        stats[2 * blockIdx.x + 1] = rsqrtf(var + 1e-5f);
    }
}

__global__ void gn_apply_t_kernel(const float* __restrict__ x, const float* __restrict__ stats,
                                  const float* __restrict__ sc, const float* __restrict__ bi,
                                  float* __restrict__ hgn) {
    __shared__ float t[32][33];
    const int b = blockIdx.z;
    const int c0 = blockIdx.y * 32;
    const int s0 = blockIdx.x * 32;
    const int tx = threadIdx.x, ty = threadIdx.y;
#pragma unroll
    for (int r = 0; r < 4; r++) {
        int c = c0 + ty + r * 8;
        int bg = b * 8 + (c >> 6);
        float mean = stats[2 * bg], rstd = stats[2 * bg + 1];
        float a = rstd * sc[c];
        float bb = bi[c] - mean * a;
        t[ty + r * 8][tx] = x[(size_t)b * CS + (size_t)c * S_ + s0 + tx] * a + bb;
    }
    __syncthreads();
#pragma unroll
    for (int r = 0; r < 4; r++) {
        int s = s0 + ty + r * 8;
        hgn[(size_t)b * CS + (size_t)s * C_ + c0 + tx] = t[tx][ty + r * 8];
    }
}

// V part of qkvT ([s,o] cols 1024..1535) -> Vt [dglob, t]
__global__ void vt_transpose_kernel(const float* __restrict__ qkvT, float* __restrict__ vt) {
    __shared__ float t[32][33];
    const int b = blockIdx.z;
    const int d0 = blockIdx.y * 32;
    const int t0 = blockIdx.x * 32;
    const int tx = threadIdx.x, ty = threadIdx.y;
#pragma unroll
    for (int r = 0; r < 4; r++) {
        int tt = t0 + ty + r * 8;
        t[ty + r * 8][tx] = qkvT[(size_t)b * S_ * 1536 + (size_t)tt * 1536 + 1024 + d0 + tx];
    }
    __syncthreads();
#pragma unroll
    for (int r = 0; r < 4; r++) {
        int d = d0 + ty + r * 8;
        vt[(size_t)b * CS + (size_t)d * S_ + t0 + tx] = t[tx][ty + r * 8];
    }
}

// ---------------------------------------------------------------------------
// Flash attention: per CTA one (b,h) and 128 q rows.  256 threads / 8 warps.
// SMEM: [0,64K) per-warp P slices (first 32K doubles as Q staging),
//       [64K,128K) K0|V0, [128K,192K) K1|V1.
// Q [128 x 64] k-contig (2 panels of 128B rows), K same, V [64 x 128] (4 panels).
// ---------------------------------------------------------------------------
__global__ void __launch_bounds__(256, 1) flash_kernel(
    const float* __restrict__ qkvT, const float* __restrict__ vt,
    float* __restrict__ o)
{
    extern __shared__ char sm[];
    const uint32_t sb = smem_u32(sm);
    const int tid = threadIdx.x, wid = tid >> 5, lane = tid & 31;
    const int grp = lane >> 2, tig = lane & 3;
    const int bz = blockIdx.z;
    const int b = bz >> 3, h = bz & 7;
    const int q0 = blockIdx.x * 128;
    const int wm0 = wid * 16;

    const float* Qg = qkvT + (size_t)b * S_ * 1536 + (size_t)q0 * 1536 + h * 64;
    const float* Kg = qkvT + (size_t)b * S_ * 1536 + 512 + h * 64;
    const float* Vg = vt   + (size_t)b * CS + (size_t)(h * 64) * S_;

    // per-thread staging offsets
    uint32_t qks[8]; int qkg[8];
    uint32_t vsf[8]; int vgf[8];
#pragma unroll
    for (int r = 0; r < 8; r++) {
        int li = tid + r * 256;
        int row = li >> 4, k4 = li & 15;
        qks[r] = (uint32_t)((k4 >> 3) * 16384 + row * 128 + (((k4 & 7) * 16) ^ ((row & 7) << 4)));
        qkg[r] = row * 1536 + k4 * 4;
        int d = li >> 5, t4 = li & 31;
        vsf[r] = (uint32_t)((t4 >> 3) * 8192 + d * 128 + (((t4 & 7) * 16) ^ ((d & 7) << 4)));
        vgf[r] = d * S_ + t4 * 4;
    }

    // prologue: Q -> [0,32K), K0/V0 -> [64K,128K)
    const uint32_t KB0 = sb + 65536;
#pragma unroll
    for (int r = 0; r < 8; r++) CP16(sb + qks[r], Qg + qkg[r]);
#pragma unroll
    for (int r = 0; r < 8; r++) CP16(KB0 + qks[r], Kg + qkg[r]);
#pragma unroll
    for (int r = 0; r < 8; r++) CP16(KB0 + 32768 + vsf[r], Vg + vgf[r]);
    CPCOMMIT();
    CPWAIT0();
    __syncthreads();

    // ldmatrix geometry
    const int rowA = lane & 15;
    const uint32_t kxA = (uint32_t)(lane >> 4) * 16;
    const int rowB = lane & 7;
    const uint32_t kxB = (uint32_t)((lane >> 3) & 1) * 16;
    const uint32_t swz = (uint32_t)(lane & 7) << 4;

    // Q fragments (held in registers for the whole kernel)
    uint32_t qf[8][4];
#pragma unroll
    for (int ks = 0; ks < 8; ks++) {
        uint32_t ad = sb + (uint32_t)(ks >> 2) * 16384 + (uint32_t)((wm0 + rowA) * 128)
                      + ((((uint32_t)(ks & 3) * 32) + kxA) ^ swz);
        ldsm4(qf[ks], ad);
    }
    __syncthreads();   // all warps done with Q before P slices overwrite it

    float m0 = -1e30f, m1 = -1e30f, l0 = 0.f, l1 = 0.f;
    float oacc[8][4];
#pragma unroll
    for (int nt = 0; nt < 8; nt++)
#pragma unroll
        for (int r = 0; r < 4; r++) oacc[nt][r] = 0.f;

    const uint32_t Pw = sb + (uint32_t)wid * 8192;     // warp-private P slice [16 x 128]

    for (int kv = 0; kv < 8; kv++) {
        const uint32_t Kb = sb + 65536 + (uint32_t)(kv & 1) * 65536;
        const uint32_t Vb = Kb + 32768;

        // issue next K/V loads
        if (kv + 1 < 8) {
            const uint32_t Kn = sb + 65536 + (uint32_t)((kv + 1) & 1) * 65536;
            const float* Kg2 = Kg + (size_t)(kv + 1) * 128 * 1536;
            const float* Vg2 = Vg + (kv + 1) * 128;
#pragma unroll
            for (int r = 0; r < 8; r++) CP16(Kn + qks[r], Kg2 + qkg[r]);
#pragma unroll
            for (int r = 0; r < 8; r++) CP16(Kn + 32768 + vsf[r], Vg2 + vgf[r]);
            CPCOMMIT();
        }

        // ---- S = Q K^T  (m=16 rows, n=128 t, k=64) ----
        float sacc[16][4];
#pragma unroll
        for (int nt = 0; nt < 16; nt++)
#pragma unroll
            for (int r = 0; r < 4; r++) sacc[nt][r] = 0.f;
#pragma unroll
        for (int ks = 0; ks < 8; ks++) {
#pragma unroll
            for (int nt = 0; nt < 16; nt++) {
                uint32_t bf[2];
                uint32_t bd = Kb + (uint32_t)(ks >> 2) * 16384 + (uint32_t)((nt * 8 + rowB) * 128)
                              + ((((uint32_t)(ks & 3) * 32) + kxB) ^ swz);
                ldsm2(bf, bd);
                mma_tf32(sacc[nt], qf[ks], bf);
            }
        }

        // ---- online softmax ----
        float r0 = -1e30f, r1 = -1e30f;
#pragma unroll
        for (int nt = 0; nt < 16; nt++) {
            r0 = fmaxf(r0, fmaxf(sacc[nt][0], sacc[nt][1]));
            r1 = fmaxf(r1, fmaxf(sacc[nt][2], sacc[nt][3]));
        }
        r0 = fmaxf(r0, __shfl_xor_sync(0xffffffffu, r0, 1));
        r0 = fmaxf(r0, __shfl_xor_sync(0xffffffffu, r0, 2));
        r1 = fmaxf(r1, __shfl_xor_sync(0xffffffffu, r1, 1));
        r1 = fmaxf(r1, __shfl_xor_sync(0xffffffffu, r1, 2));
        float mn0 = fmaxf(m0, r0), mn1 = fmaxf(m1, r1);
        float a0 = exp2f((m0 - mn0) * CEXP);
        float a1 = exp2f((m1 - mn1) * CEXP);
        m0 = mn0; m1 = mn1;
        l0 *= a0; l1 *= a1;
#pragma unroll
        for (int nt = 0; nt < 8; nt++) {
            oacc[nt][0] *= a0; oacc[nt][1] *= a0;
            oacc[nt][2] *= a1; oacc[nt][3] *= a1;
        }
        const uint32_t key = (uint32_t)grp << 4;
        const uint32_t pbase = (uint32_t)wid * 8192 + (uint32_t)grp * 128;
#pragma unroll
        for (int nt = 0; nt < 16; nt++) {
            float p0 = exp2f((sacc[nt][0] - m0) * CEXP);
            float p1 = exp2f((sacc[nt][1] - m0) * CEXP);
            float p2 = exp2f((sacc[nt][2] - m1) * CEXP);
            float p3 = exp2f((sacc[nt][3] - m1) * CEXP);
            l0 += p0 + p1; l1 += p2 + p3;
            int t = nt * 8 + tig * 2;
            uint32_t off = pbase + (uint32_t)(t >> 5) * 2048 + (((uint32_t)(t & 31) * 4) ^ key);
            *(float2*)(sm + off)        = make_float2(p0, p1);
            *(float2*)(sm + off + 1024) = make_float2(p2, p3);   // row grp+8
        }
        __syncwarp();

        // ---- O += P V  (m=16 s, n=64 d, k=128 t) ----
#pragma unroll
        for (int kt = 0; kt < 16; kt++) {
            uint32_t pf[4];
            uint32_t ad = Pw + (uint32_t)(kt >> 2) * 2048 + (uint32_t)(rowA * 128)
                          + ((((uint32_t)(kt & 3) * 32) + kxA) ^ swz);
            ldsm4(pf, ad);
#pragma unroll
            for (int nt = 0; nt < 8; nt++) {
                uint32_t bf[2];
                uint32_t bd = Vb + (uint32_t)(kt >> 2) * 8192 + (uint32_t)((nt * 8 + rowB) * 128)
                              + ((((uint32_t)(kt & 3) * 32) + kxB) ^ swz);
                ldsm2(bf, bd);
                mma_tf32(oacc[nt], pf, bf);
            }
        }

        if (kv + 1 < 8) CPWAIT0();
        __syncthreads();
    }

    // ---- finalize: normalize and store to o [b, s, 512] ----
    l0 += __shfl_xor_sync(0xffffffffu, l0, 1);
    l0 += __shfl_xor_sync(0xffffffffu, l0, 2);
    l1 += __shfl_xor_sync(0xffffffffu, l1, 1);
    l1 += __shfl_xor_sync(0xffffffffu, l1, 2);
    float i0 = 1.f / l0, i1 = 1.f / l1;
    const int sg = q0 + wm0 + grp;
    float* ob = o + (size_t)b * CS + (size_t)sg * 512 + h * 64 + tig * 2;
#pragma unroll
    for (int nt = 0; nt < 8; nt++) {
        *(float2*)(ob + nt * 8)            = make_float2(oacc[nt][0] * i0, oacc[nt][1] * i0);
        *(float2*)(ob + 8 * 512 + nt * 8)  = make_float2(oacc[nt][2] * i1, oacc[nt][3] * i1);
    }
}

// ---------------------------------------------------------------------------
// mma.sync tf32 GEMM:  D[m,n] = epi( scale * sum_k A[m,k]*B[n,k] )
// A: [M,K] K-contig (ldA), B: [N,K] K-contig (ldB). BM=128, BN=128, BK=32.
// EPI: 0 plain (O[n*ldO+m]); 1 INL tanh; 2 residual
// BIAS_MODE: 0 none, 1 bias[m], 2 bias[n]
// ---------------------------------------------------------------------------
template <int BN, int EPI, int BIAS_MODE>
__global__ void __launch_bounds__(256) mm_kernel(
    const float* __restrict__ Abase, int ldA, size_t sAo, size_t sAi,
    const float* __restrict__ Bbase, int ldB, size_t sBo, size_t sBi,
    float* __restrict__ Obase, int ldO, size_t sOo, size_t sOi,
    const float* __restrict__ bias,
    const float* __restrict__ Ebase, size_t sEo, size_t sEi,
    int K, int inner, float scale)
{
    constexpr int ABYTES = 128 * 128;
    constexpr int BBYTES = BN * 128;
    constexpr int STAGE  = ABYTES + BBYTES;
    constexpr int BF4    = BN / 32;
    constexpr int WARPS_M = (BN == 128) ? 2 : 4;
    constexpr int MT = 128 / WARPS_M / 16;
    constexpr int PITCH = 132;

    extern __shared__ char smemc[];
    const uint32_t sb = smem_u32(smemc);
    const int tid = threadIdx.x;
    const int wid = tid >> 5;
    const int lane = tid & 31;
    const int grp = lane >> 2, tig = lane & 3;

    const int z = blockIdx.z;
    const int zo = z / inner;
    const int zi = z - zo * inner;
    const float* Ag = Abase + zo * sAo + zi * sAi;
    const float* Bg = Bbase + zo * sBo + zi * sBi;
    float*       O  = Obase + zo * sOo + zi * sOi;
    const float* E  = (EPI == 1 || EPI == 2) ? (Ebase + zo * sEo + zi * sEi) : nullptr;

    const int m0 = blockIdx.y * 128;
    const int n0 = blockIdx.x * BN;

    const int wm0 = (BN == 128) ? (wid & 1) * 64 : (wid & 3) * 32;
    const int wn0 = (BN == 128) ? (wid >> 1) * 32 : (wid >> 2) * 32;

    const float* aptr[4];
    uint32_t asw[4];
#pragma unroll
    for (int r = 0; r < 4; r++) {
        int li = tid + r * 256;
        int row = li >> 3, k4 = li & 7;
        aptr[r] = Ag + (size_t)(m0 + row) * ldA + k4 * 4;
        asw[r] = (uint32_t)(row * 128 + k4 * 16) ^ ((uint32_t)(row & 7) << 4);
    }
    const float* bptr[BF4];
    uint32_t bsw[BF4];
#pragma unroll
    for (int r = 0; r < BF4; r++) {
        int li = tid + r * 256;
        int row = li >> 3, k4 = li & 7;
        bptr[r] = Bg + (size_t)(n0 + row) * ldB + k4 * 4;
        bsw[r] = (uint32_t)(row * 128 + k4 * 16) ^ ((uint32_t)(row & 7) << 4);
    }

    const int rowA = (lane & 7) + ((lane >> 3) & 1) * 8;
    const uint32_t kxA = ((uint32_t)(lane >> 4)) * 16;
    const int rowB = lane & 7;
    const uint32_t kxB = ((uint32_t)((lane >> 3) & 1)) * 16;
    const uint32_t swz = ((uint32_t)(lane & 7)) << 4;

    float acc[MT][4][4];
#pragma unroll
    for (int mt = 0; mt < MT; mt++)
#pragma unroll
        for (int nt = 0; nt < 4; nt++)
#pragma unroll
            for (int r = 0; r < 4; r++) acc[mt][nt][r] = 0.f;

    const int nkt = K >> 5;

    {
#pragma unroll
        for (int r = 0; r < 4; r++) {
            float4 v = *(const float4*)(aptr[r]);
            v.x = rtf32(v.x); v.y = rtf32(v.y); v.z = rtf32(v.z); v.w = rtf32(v.w);
            *(float4*)(smemc + asw[r]) = v;
        }
#pragma unroll
        for (int r = 0; r < BF4; r++) {
            float4 v = *(const float4*)(bptr[r]);
            v.x = rtf32(v.x); v.y = rtf32(v.y); v.z = rtf32(v.z); v.w = rtf32(v.w);
            *(float4*)(smemc + ABYTES + bsw[r]) = v;
        }
    }
    __syncthreads();

    for (int kt = 0; kt < nkt; kt++) {
        const int cur = kt & 1;
        const uint32_t As = sb + cur * STAGE;
        const uint32_t Bs = As + ABYTES;

        float4 pa[4], pb[BF4];
        if (kt + 1 < nkt) {
            const int k0 = (kt + 1) << 5;
#pragma unroll
            for (int r = 0; r < 4; r++) pa[r] = *(const float4*)(aptr[r] + k0);
#pragma unroll
            for (int r = 0; r < BF4; r++) pb[r] = *(const float4*)(bptr[r] + k0);
        }

#pragma unroll
        for (int ks = 0; ks < 4; ks++) {
            uint32_t afr[MT][4];
#pragma unroll
            for (int mt = 0; mt < MT; mt++) {
                uint32_t ad = As + (uint32_t)((wm0 + mt * 16 + rowA) * 128) + (((uint32_t)(ks * 32) + kxA) ^ swz);
                ldsm4(afr[mt], ad);
            }
            uint32_t bfr[4][2];
#pragma unroll
            for (int nt = 0; nt < 4; nt++) {
                uint32_t bd = Bs + (uint32_t)((wn0 + nt * 8 + rowB) * 128) + (((uint32_t)(ks * 32) + kxB) ^ swz);
                ldsm2(bfr[nt], bd);
            }
#pragma unroll
            for (int mt = 0; mt < MT; mt++)
#pragma unroll
                for (int nt = 0; nt < 4; nt++)
                    mma_tf32(acc[mt][nt], afr[mt], bfr[nt]);
        }

        if (kt + 1 < nkt) {
            char* As2 = smemc + (cur ^ 1) * STAGE;
#pragma unroll
            for (int r = 0; r < 4; r++) {
                float4 v = pa[r];
                v.x = rtf32(v.x); v.y = rtf32(v.y); v.z = rtf32(v.z); v.w = rtf32(v.w);
                *(float4*)(As2 + asw[r]) = v;
            }
#pragma unroll
            for (int r = 0; r < BF4; r++) {
                float4 v = pb[r];
                v.x = rtf32(v.x); v.y = rtf32(v.y); v.z = rtf32(v.z); v.w = rtf32(v.w);
                *(float4*)(As2 + ABYTES + bsw[r]) = v;
            }
            __syncthreads();
        }
    }

    __syncthreads();
    float* Csm = (float*)smemc;

#pragma unroll
    for (int mt = 0; mt < MT; mt++) {
#pragma unroll
        for (int nt = 0; nt < 4; nt++) {
            int m = wm0 + mt * 16 + grp;
            int n = wn0 + nt * 8 + tig * 2;
            Csm[(n)     * PITCH + m]     = acc[mt][nt][0];
            Csm[(n + 1) * PITCH + m]     = acc[mt][nt][1];
            Csm[(n)     * PITCH + m + 8] = acc[mt][nt][2];
            Csm[(n + 1) * PITCH + m + 8] = acc[mt][nt][3];
        }
    }
    __syncthreads();

#pragma unroll
    for (int it = 0; it < BN / 8; it++) {
        int li = tid + it * 256;
        int n = li >> 5, m4 = (li & 31) << 2;
        float4 c = *(float4*)(Csm + n * PITCH + m4);
        c.x *= scale; c.y *= scale; c.z *= scale; c.w *= scale;
        if (BIAS_MODE == 1) {
            float4 bm = *(const float4*)(bias + m0 + m4);
            c.x += bm.x; c.y += bm.y; c.z += bm.z; c.w += bm.w;
        } else if (BIAS_MODE == 2) {
            float bn = bias[n0 + n];
            c.x += bn; c.y += bn; c.z += bn; c.w += bn;
        }
        size_t idx = (size_t)(n0 + n) * ldO + m0 + m4;
        if (EPI == 1) {
            float4 e = *(const float4*)(E + idx);
            c.x = e.x + 0.1f * tanhf(c.x); c.y = e.y + 0.1f * tanhf(c.y);
            c.z = e.z + 0.1f * tanhf(c.z); c.w = e.w + 0.1f * tanhf(c.w);
        } else if (EPI == 2) {
            float4 e = *(const float4*)(E + idx);
            c.x += e.x; c.y += e.y; c.z += e.z; c.w += e.w;
        }
        *(float4*)(O + idx) = c;
    }
}

// ---------------------------------------------------------------------------
// Host launcher
// ---------------------------------------------------------------------------
extern "C" void kernel_launch(void* const* d_in, const int* in_sizes, int n_in,
                              void* d_out, int out_size) {
    const float* x        = (const float*)d_in[0];
    const float* gn_scale = (const float*)d_in[1];
    const float* gn_bias  = (const float*)d_in[2];
    const float* qkv_w    = (const float*)d_in[3];
    const float* qkv_b    = (const float*)d_in[4];
    const float* proj_w   = (const float*)d_in[5];
    const float* proj_b   = (const float*)d_in[6];
    const float* inl_w    = (const float*)d_in[7];
    const float* inl_b    = (const float*)d_in[8];
    float* out = (float*)d_out;

    float *hgn, *qkvT, *vt, *h1, *h2, *stats;
    cudaGetSymbolAddress((void**)&hgn,    g_hgn);
    cudaGetSymbolAddress((void**)&qkvT,   g_qkvT);
    cudaGetSymbolAddress((void**)&vt,     g_vt);
    cudaGetSymbolAddress((void**)&h1,     g_h1);
    cudaGetSymbolAddress((void**)&h2,     g_h2);
    cudaGetSymbolAddress((void**)&stats,  g_stats);

    const int SM128 = 132 * 128 * 4;   // 67584
    const int SMFL  = 196608;          // flash: 64K P/Q + 2x64K K/V
    cudaFuncSetAttribute(mm_kernel<128, 0, 1>, cudaFuncAttributeMaxDynamicSharedMemorySize, SM128);
    cudaFuncSetAttribute(mm_kernel<128, 1, 1>, cudaFuncAttributeMaxDynamicSharedMemorySize, SM128);
    cudaFuncSetAttribute(mm_kernel<128, 2, 2>, cudaFuncAttributeMaxDynamicSharedMemorySize, SM128);
    cudaFuncSetAttribute(flash_kernel, cudaFuncAttributeMaxDynamicSharedMemorySize, SMFL);

    const size_t CSz = (size_t)CS;

    // 1) GroupNorm (stats) + apply-with-transpose -> hgn [b, s, c]
    gn_stats_kernel<<<B_ * NH, 256>>>(x, stats);
    gn_apply_t_kernel<<<dim3(32, 16, B_), dim3(32, 8)>>>(x, stats, gn_scale, gn_bias, hgn);

    // 2) QKV: qkvT[s, o] = qkv_w[o,:].hgn[s,:] + qkv_b[o]
    mm_kernel<128, 0, 1><<<dim3(8, 12, B_), 256, SM128>>>(
        qkv_w, C_, 0, 0,
        hgn, C_, CSz, 0,
        qkvT, 1536, (size_t)S_ * 1536, 0,
        qkv_b, nullptr, 0, 0,
        C_, 1, 1.f);

    // 3) Vt: V part of qkvT -> [dglob, t]
    vt_transpose_kernel<<<dim3(32, 16, B_), dim3(32, 8)>>>(qkvT, vt);

    // 4) fused attention -> h1 [b, s, c]
    flash_kernel<<<dim3(8, 1, B_ * NH), 256, SMFL>>>(qkvT, vt, h1);

    // 5) INL x3: dst[s][o] = src[s][o] + 0.1*tanh(inl_w[o,:].src[s,:] + inl_b[o])
    const float* src = h1;
    float* dst = h2;
    for (int it = 0; it < 3; it++) {
        mm_kernel<128, 1, 1><<<dim3(8, 4, B_), 256, SM128>>>(
            inl_w, C_, 0, 0,
            src, C_, CSz, 0,
            dst, C_, CSz, 0,
            inl_b, src, CSz, 0,
            C_, 1, 1.f);
        const float* t = src; src = dst; dst = (float*)t;
    }

    // 6) proj + residual: out[o][s] = x[o][s] + proj_w[o,:].src[s,:] + proj_b[o]
    mm_kernel<128, 2, 2><<<dim3(4, 8, B_), 256, SM128>>>(
        src, C_, CSz, 0,
        proj_w, C_, 0, 0,
        out, S_, CSz, 0,
        proj_b, x, CSz, 0,
        C_, 1, 1.f);
}

// round 5
// speedup vs baseline: 4.7364x; 1.3471x over previous
#include <cuda_runtime.h>
#include <cuda_fp16.h>
#include <cstdint>
#include <cstddef>

// ===========================================================================
// INLAttentionBlock, fp16 tensor-core pipeline (mma.sync m16n8k16, f32 accum):
// GN+T -> QKV -> flash(QK+softmax+PV) -> 3x INL -> proj+res
// B=8, C=512, S=1024, nh=8, hd=64. Activations token-major [b, s, c].
// MMA operands fp16; residual/Euler state kept in fp32 shadows.
// ===========================================================================

#define B_ 8
#define C_ 512
#define S_ 1024
#define NH 8
#define CS (C_ * S_)
#define CEXP 0.18033688011112042f   // 0.125 * log2(e)

__device__ __half g_hgn[(size_t)B_ * S_ * C_];        // [b, s, c] fp16
__device__ __half g_qkvT[(size_t)B_ * S_ * 1536];     // [b, s, 3C] fp16
__device__ float  g_h1f[(size_t)B_ * S_ * C_];        // fp32 shadow
__device__ __half g_h1h[(size_t)B_ * S_ * C_];
__device__ float  g_h2f[(size_t)B_ * S_ * C_];
__device__ __half g_h2h[(size_t)B_ * S_ * C_];
__device__ __half g_w16[1310720];                     // qkv|inl|proj fp16 weights
__device__ float  g_stats[2 * B_ * NH];

// ---------------------------------------------------------------------------
// helpers
// ---------------------------------------------------------------------------
__device__ __forceinline__ uint32_t smem_u32(const void* p) {
    uint32_t a;
    asm("{ .reg .u64 t; cvta.to.shared.u64 t, %1; cvt.u32.u64 %0, t; }" : "=r"(a) : "l"(p));
    return a;
}
__device__ __forceinline__ void ldsm4(uint32_t* r, uint32_t addr) {
    asm volatile("ldmatrix.sync.aligned.m8n8.x4.shared.b16 {%0,%1,%2,%3}, [%4];"
                 : "=r"(r[0]), "=r"(r[1]), "=r"(r[2]), "=r"(r[3]) : "r"(addr));
}
__device__ __forceinline__ void ldsm2(uint32_t* r, uint32_t addr) {
    asm volatile("ldmatrix.sync.aligned.m8n8.x2.shared.b16 {%0,%1}, [%2];"
                 : "=r"(r[0]), "=r"(r[1]) : "r"(addr));
}
__device__ __forceinline__ void ldsm2t(uint32_t* r, uint32_t addr) {
    asm volatile("ldmatrix.sync.aligned.m8n8.x2.trans.shared.b16 {%0,%1}, [%2];"
                 : "=r"(r[0]), "=r"(r[1]) : "r"(addr));
}
__device__ __forceinline__ void mma16(float* d, const uint32_t* a, const uint32_t* b) {
    asm volatile("mma.sync.aligned.m16n8k16.row.col.f32.f16.f16.f32 "
                 "{%0,%1,%2,%3}, {%4,%5,%6,%7}, {%8,%9}, {%0,%1,%2,%3};"
                 : "+f"(d[0]), "+f"(d[1]), "+f"(d[2]), "+f"(d[3])
                 : "r"(a[0]), "r"(a[1]), "r"(a[2]), "r"(a[3]), "r"(b[0]), "r"(b[1]));
}
#define CP16(sa, ga) asm volatile("cp.async.cg.shared.global [%0], [%1], 16;" :: "r"(sa), "l"((const void*)(ga)))
#define CPCOMMIT()   asm volatile("cp.async.commit_group;" ::: "memory")
#define CPWAIT0()    asm volatile("cp.async.wait_group 0;" ::: "memory")

// ---------------------------------------------------------------------------
// fp32 -> fp16 convert (weights). n multiple of 2048.
// ---------------------------------------------------------------------------
__global__ void f2h_kernel(const float* __restrict__ s, __half* __restrict__ d) {
    int i = (blockIdx.x * 256 + threadIdx.x) * 8;
    float4 a = *(const float4*)(s + i);
    float4 b = *(const float4*)(s + i + 4);
    union { __half2 h[4]; uint4 u; } pk;
    pk.h[0] = __floats2half2_rn(a.x, a.y);
    pk.h[1] = __floats2half2_rn(a.z, a.w);
    pk.h[2] = __floats2half2_rn(b.x, b.y);
    pk.h[3] = __floats2half2_rn(b.z, b.w);
    *(uint4*)(d + i) = pk.u;
}

// ---------------------------------------------------------------------------
// GroupNorm stats + apply-with-transpose ([c,s] fp32 -> [s,c] fp16)
// ---------------------------------------------------------------------------
__global__ void gn_stats_kernel(const float* __restrict__ x, float* __restrict__ stats) {
    __shared__ float sh[256], sh2[256];
    const int tid = threadIdx.x;
    const float4* p = (const float4*)(x + (size_t)blockIdx.x * 65536);
    float s = 0.f, s2 = 0.f;
    for (int i = tid; i < 16384; i += 256) {
        float4 v = p[i];
        s  += v.x + v.y + v.z + v.w;
        s2 += v.x * v.x + v.y * v.y + v.z * v.z + v.w * v.w;
    }
    sh[tid] = s; sh2[tid] = s2;
    __syncthreads();
    for (int st = 128; st > 0; st >>= 1) {
        if (tid < st) { sh[tid] += sh[tid + st]; sh2[tid] += sh2[tid + st]; }
        __syncthreads();
    }
    if (tid == 0) {
        float mean = sh[0] * (1.f / 65536.f);
        float var  = sh2[0] * (1.f / 65536.f) - mean * mean;
        stats[2 * blockIdx.x]     = mean;
        stats[2 * blockIdx.x + 1] = rsqrtf(var + 1e-5f);
    }
}

__global__ void gn_apply_t_kernel(const float* __restrict__ x, const float* __restrict__ stats,
                                  const float* __restrict__ sc, const float* __restrict__ bi,
                                  __half* __restrict__ hgn) {
    __shared__ float t[32][33];
    const int b = blockIdx.z;
    const int c0 = blockIdx.y * 32;
    const int s0 = blockIdx.x * 32;
    const int tx = threadIdx.x, ty = threadIdx.y;
#pragma unroll
    for (int r = 0; r < 4; r++) {
        int c = c0 + ty + r * 8;
        int bg = b * 8 + (c >> 6);
        float mean = stats[2 * bg], rstd = stats[2 * bg + 1];
        float a = rstd * sc[c];
        float bb = bi[c] - mean * a;
        t[ty + r * 8][tx] = x[(size_t)b * CS + (size_t)c * S_ + s0 + tx] * a + bb;
    }
    __syncthreads();
#pragma unroll
    for (int r = 0; r < 4; r++) {
        int s = s0 + ty + r * 8;
        hgn[(size_t)b * CS + (size_t)s * C_ + c0 + tx] = __float2half_rn(t[tx][ty + r * 8]);
    }
}

// ---------------------------------------------------------------------------
// Flash attention fp16: CTA = (b,h, 128 q rows). 256 thr / 8 warps.
// SMEM: [0,32K) warp P slices (Q staged in [0,16K) first),
//       [32K,64K) K0|V0, [64K,96K) K1|V1. K,V tiles: [t(128) x 64h] 128B rows.
// ---------------------------------------------------------------------------
__global__ void __launch_bounds__(256, 1) flash_kernel(
    const __half* __restrict__ qkvT, float* __restrict__ of, __half* __restrict__ oh)
{
    extern __shared__ char sm[];
    const uint32_t sb = smem_u32(sm);
    const int tid = threadIdx.x, wid = tid >> 5, lane = tid & 31;
    const int grp = lane >> 2, tig = lane & 3;
    const int b = blockIdx.z >> 3, h = blockIdx.z & 7;
    const int q0 = blockIdx.x * 128;
    const int wm0 = wid * 16;

    const __half* Qg = qkvT + (size_t)b * S_ * 1536 + (size_t)q0 * 1536 + h * 64;
    const __half* Kg = qkvT + (size_t)b * S_ * 1536 + 512 + h * 64;

    // cp.async per-thread offsets (tile [128 rows x 64 halves], 128B rows, SW)
    uint32_t so[4]; int go[4];
#pragma unroll
    for (int r = 0; r < 4; r++) {
        int li = tid + r * 256;
        int row = li >> 3, c8 = li & 7;
        so[r] = (uint32_t)(row * 128 + c8 * 16) ^ ((uint32_t)(row & 7) << 4);
        go[r] = row * 1536 + c8 * 8;
    }

    // prologue: Q -> [0,16K); K0/V0 -> [32K,64K)
    const uint32_t KV0 = sb + 32768;
#pragma unroll
    for (int r = 0; r < 4; r++) CP16(sb + so[r], Qg + go[r]);
#pragma unroll
    for (int r = 0; r < 4; r++) CP16(KV0 + so[r], Kg + go[r]);
#pragma unroll
    for (int r = 0; r < 4; r++) CP16(KV0 + 16384 + so[r], Kg + 512 + go[r]);
    CPCOMMIT(); CPWAIT0();
    __syncthreads();

    const int rowA = lane & 15;
    const uint32_t kxA = (uint32_t)(lane >> 4) * 16;
    const uint32_t swzA = (uint32_t)(rowA & 7) << 4;
    const int rowB = lane & 7;
    const uint32_t kxB = (uint32_t)((lane >> 3) & 1) * 16;

    // Q fragments: K=64 -> 4 k16 steps
    uint32_t qf[4][4];
#pragma unroll
    for (int ks = 0; ks < 4; ks++)
        ldsm4(qf[ks], sb + (uint32_t)((wm0 + rowA) * 128) + (((uint32_t)(ks * 32) + kxA) ^ swzA));
    __syncthreads();

    float m0 = -1e30f, m1 = -1e30f, l0 = 0.f, l1 = 0.f;
    float oacc[8][4];
#pragma unroll
    for (int nt = 0; nt < 8; nt++)
#pragma unroll
        for (int r = 0; r < 4; r++) oacc[nt][r] = 0.f;

    const uint32_t Pw = sb + (uint32_t)wid * 4096;   // [16 rows x 128 t] fp16, 2 panels

    for (int kv = 0; kv < 8; kv++) {
        const uint32_t Kb = sb + 32768 + (uint32_t)(kv & 1) * 32768;
        const uint32_t Vb = Kb + 16384;

        if (kv + 1 < 8) {
            const uint32_t Kn = sb + 32768 + (uint32_t)((kv + 1) & 1) * 32768;
            const __half* Kg2 = Kg + (size_t)(kv + 1) * 128 * 1536;
#pragma unroll
            for (int r = 0; r < 4; r++) CP16(Kn + so[r], Kg2 + go[r]);
#pragma unroll
            for (int r = 0; r < 4; r++) CP16(Kn + 16384 + so[r], Kg2 + 512 + go[r]);
            CPCOMMIT();
        }

        // ---- S = Q K^T  (16 x 128, k=64) ----
        float sacc[16][4];
#pragma unroll
        for (int nt = 0; nt < 16; nt++)
#pragma unroll
            for (int r = 0; r < 4; r++) sacc[nt][r] = 0.f;
#pragma unroll
        for (int ks = 0; ks < 4; ks++) {
#pragma unroll
            for (int nt = 0; nt < 16; nt++) {
                uint32_t bf[2];
                ldsm2(bf, Kb + (uint32_t)((nt * 8 + rowB) * 128)
                          + (((uint32_t)(ks * 32) + kxB) ^ ((uint32_t)rowB << 4)));
                mma16(sacc[nt], qf[ks], bf);
            }
        }

        // ---- online softmax ----
        float r0 = -1e30f, r1 = -1e30f;
#pragma unroll
        for (int nt = 0; nt < 16; nt++) {
            r0 = fmaxf(r0, fmaxf(sacc[nt][0], sacc[nt][1]));
            r1 = fmaxf(r1, fmaxf(sacc[nt][2], sacc[nt][3]));
        }
        r0 = fmaxf(r0, __shfl_xor_sync(0xffffffffu, r0, 1));
        r0 = fmaxf(r0, __shfl_xor_sync(0xffffffffu, r0, 2));
        r1 = fmaxf(r1, __shfl_xor_sync(0xffffffffu, r1, 1));
        r1 = fmaxf(r1, __shfl_xor_sync(0xffffffffu, r1, 2));
        float mn0 = fmaxf(m0, r0), mn1 = fmaxf(m1, r1);
        float a0 = exp2f((m0 - mn0) * CEXP);
        float a1 = exp2f((m1 - mn1) * CEXP);
        m0 = mn0; m1 = mn1;
        l0 *= a0; l1 *= a1;
#pragma unroll
        for (int nt = 0; nt < 8; nt++) {
            oacc[nt][0] *= a0; oacc[nt][1] *= a0;
            oacc[nt][2] *= a1; oacc[nt][3] *= a1;
        }
#pragma unroll
        for (int nt = 0; nt < 16; nt++) {
            float p0 = exp2f((sacc[nt][0] - m0) * CEXP);
            float p1 = exp2f((sacc[nt][1] - m0) * CEXP);
            float p2 = exp2f((sacc[nt][2] - m1) * CEXP);
            float p3 = exp2f((sacc[nt][3] - m1) * CEXP);
            l0 += p0 + p1; l1 += p2 + p3;
            int t = nt * 8 + tig * 2;
            uint32_t off = (Pw - sb) + (uint32_t)(t >> 6) * 2048 + (uint32_t)(grp * 128)
                           + (((uint32_t)(t & 63) * 2) ^ ((uint32_t)grp << 4));
            *(__half2*)(sm + off)        = __floats2half2_rn(p0, p1);
            *(__half2*)(sm + off + 1024) = __floats2half2_rn(p2, p3);  // row grp+8
        }
        __syncwarp();

        // ---- O += P V  (16 x 64, k=128; V via ldsm.trans) ----
#pragma unroll
        for (int kt = 0; kt < 8; kt++) {
            uint32_t pf[4];
            ldsm4(pf, Pw + (uint32_t)(kt >> 2) * 2048 + (uint32_t)(rowA * 128)
                      + (((uint32_t)((kt & 3) * 32) + kxA) ^ swzA));
#pragma unroll
            for (int nt = 0; nt < 8; nt++) {
                uint32_t bf[2];
                ldsm2t(bf, Vb + (uint32_t)((kt * 16 + rowA) * 128)
                           + (((uint32_t)(nt * 16)) ^ swzA));
                mma16(oacc[nt], pf, bf);
            }
        }

        if (kv + 1 < 8) CPWAIT0();
        __syncthreads();
    }

    // ---- finalize ----
    l0 += __shfl_xor_sync(0xffffffffu, l0, 1);
    l0 += __shfl_xor_sync(0xffffffffu, l0, 2);
    l1 += __shfl_xor_sync(0xffffffffu, l1, 1);
    l1 += __shfl_xor_sync(0xffffffffu, l1, 2);
    float i0 = 1.f / l0, i1 = 1.f / l1;
    const int sg = q0 + wm0 + grp;
    size_t ob = (size_t)b * CS + (size_t)sg * 512 + h * 64 + tig * 2;
#pragma unroll
    for (int nt = 0; nt < 8; nt++) {
        float x0 = oacc[nt][0] * i0, x1 = oacc[nt][1] * i0;
        float x2 = oacc[nt][2] * i1, x3 = oacc[nt][3] * i1;
        *(float2*)(of + ob + nt * 8)            = make_float2(x0, x1);
        *(float2*)(of + ob + 8 * 512 + nt * 8)  = make_float2(x2, x3);
        *(__half2*)(oh + ob + nt * 8)           = __floats2half2_rn(x0, x1);
        *(__half2*)(oh + ob + 8 * 512 + nt * 8) = __floats2half2_rn(x2, x3);
    }
}

// ---------------------------------------------------------------------------
// fp16 GEMM: D[m,n] = epi( sum_k A[m,k]*B[n,k] ), A/B fp16 K-contig.
// BM=128, BN=128, BK=64. EPI: 0 QKV(out fp16, +bias[m]);
// 1 INL(out f32+f16, E + 0.1*tanh(v+bias[m])); 2 proj(out f32, E + v + bias[n]).
// ---------------------------------------------------------------------------
template <int EPI>
__global__ void __launch_bounds__(256) mm16_kernel(
    const __half* __restrict__ Abase, int ldA, size_t sAo,
    const __half* __restrict__ Bbase, int ldB, size_t sBo,
    float* __restrict__ O32, __half* __restrict__ O16, int ldO, size_t sOo,
    const float* __restrict__ bias,
    const float* __restrict__ Ebase, size_t sEo,
    int K)
{
    constexpr int ABYTES = 16384;       // 128 x 64 halves
    constexpr int STAGE  = 32768;
    constexpr int PITCH  = 132;

    extern __shared__ char smemc[];
    const uint32_t sb = smem_u32(smemc);
    const int tid = threadIdx.x;
    const int wid = tid >> 5;
    const int lane = tid & 31;
    const int grp = lane >> 2, tig = lane & 3;

    const int z = blockIdx.z;
    const __half* Ag = Abase + (size_t)z * sAo;
    const __half* Bg = Bbase + (size_t)z * sBo;
    const float*  E  = (EPI != 0) ? (Ebase + (size_t)z * sEo) : nullptr;

    const int m0 = blockIdx.y * 128;
    const int n0 = blockIdx.x * 128;
    const int wm0 = (wid & 1) * 64;
    const int wn0 = (wid >> 1) * 32;

    uint32_t asw[4], bsw[4];
    size_t ago[4], bgo[4];
#pragma unroll
    for (int r = 0; r < 4; r++) {
        int li = tid + r * 256;
        int row = li >> 3, c8 = li & 7;
        uint32_t sw = (uint32_t)(row * 128 + c8 * 16) ^ ((uint32_t)(row & 7) << 4);
        asw[r] = sw; bsw[r] = sw;
        ago[r] = (size_t)(m0 + row) * ldA + c8 * 8;
        bgo[r] = (size_t)(n0 + row) * ldB + c8 * 8;
    }

    const int rowA = lane & 15;
    const uint32_t kxA = (uint32_t)(lane >> 4) * 16;
    const uint32_t swzA = (uint32_t)(rowA & 7) << 4;
    const int rowB = lane & 7;
    const uint32_t kxB = (uint32_t)((lane >> 3) & 1) * 16;

    float acc[4][4][4];
#pragma unroll
    for (int mt = 0; mt < 4; mt++)
#pragma unroll
        for (int nt = 0; nt < 4; nt++)
#pragma unroll
            for (int r = 0; r < 4; r++) acc[mt][nt][r] = 0.f;

    const int nkt = K >> 6;

    // prologue: tile 0
#pragma unroll
    for (int r = 0; r < 4; r++) { CP16(sb + asw[r], Ag + ago[r]); CP16(sb + ABYTES + bsw[r], Bg + bgo[r]); }
    CPCOMMIT(); CPWAIT0();
    __syncthreads();

    for (int kt = 0; kt < nkt; kt++) {
        const int cur = kt & 1;
        const uint32_t As = sb + cur * STAGE;
        const uint32_t Bs = As + ABYTES;

        if (kt + 1 < nkt) {
            const uint32_t nb = sb + (cur ^ 1) * STAGE;
            const int k0 = (kt + 1) << 6;
#pragma unroll
            for (int r = 0; r < 4; r++) { CP16(nb + asw[r], Ag + ago[r] + k0); CP16(nb + ABYTES + bsw[r], Bg + bgo[r] + k0); }
            CPCOMMIT();
        }

#pragma unroll
        for (int ks = 0; ks < 4; ks++) {
            uint32_t afr[4][4];
#pragma unroll
            for (int mt = 0; mt < 4; mt++)
                ldsm4(afr[mt], As + (uint32_t)((wm0 + mt * 16 + rowA) * 128)
                              + (((uint32_t)(ks * 32) + kxA) ^ swzA));
            uint32_t bfr[4][2];
#pragma unroll
            for (int nt = 0; nt < 4; nt++)
                ldsm2(bfr[nt], Bs + (uint32_t)((wn0 + nt * 8 + rowB) * 128)
                              + (((uint32_t)(ks * 32) + kxB) ^ ((uint32_t)rowB << 4)));
#pragma unroll
            for (int mt = 0; mt < 4; mt++)
#pragma unroll
                for (int nt = 0; nt < 4; nt++)
                    mma16(acc[mt][nt], afr[mt], bfr[nt]);
        }

        if (kt + 1 < nkt) { CPWAIT0(); __syncthreads(); }
    }

    // ---- epilogue: transpose through SMEM ([n][m] fp32) ----
    __syncthreads();
    float* Csm = (float*)smemc;
#pragma unroll
    for (int mt = 0; mt < 4; mt++) {
#pragma unroll
        for (int nt = 0; nt < 4; nt++) {
            int m = wm0 + mt * 16 + grp;
            int n = wn0 + nt * 8 + tig * 2;
            Csm[(n)     * PITCH + m]     = acc[mt][nt][0];
            Csm[(n + 1) * PITCH + m]     = acc[mt][nt][1];
            Csm[(n)     * PITCH + m + 8] = acc[mt][nt][2];
            Csm[(n + 1) * PITCH + m + 8] = acc[mt][nt][3];
        }
    }
    __syncthreads();

#pragma unroll
    for (int it = 0; it < 16; it++) {
        int li = tid + it * 256;
        int n = li >> 5, m4 = (li & 31) << 2;
        float4 c = *(float4*)(Csm + n * PITCH + m4);
        size_t idx = (size_t)z * sOo + (size_t)(n0 + n) * ldO + m0 + m4;
        if (EPI == 0) {
            float4 bm = *(const float4*)(bias + m0 + m4);
            union { __half2 h[2]; uint2 u; } pk;
            pk.h[0] = __floats2half2_rn(c.x + bm.x, c.y + bm.y);
            pk.h[1] = __floats2half2_rn(c.z + bm.z, c.w + bm.w);
            *(uint2*)(O16 + idx) = pk.u;
        } else if (EPI == 1) {
            float4 bm = *(const float4*)(bias + m0 + m4);
            float4 e = *(const float4*)(E + (size_t)(n0 + n) * ldO + m0 + m4);
            float4 r;
            r.x = e.x + 0.1f * tanhf(c.x + bm.x);
            r.y = e.y + 0.1f * tanhf(c.y + bm.y);
            r.z = e.z + 0.1f * tanhf(c.z + bm.z);
            r.w = e.w + 0.1f * tanhf(c.w + bm.w);
            *(float4*)(O32 + idx) = r;
            union { __half2 h[2]; uint2 u; } pk;
            pk.h[0] = __floats2half2_rn(r.x, r.y);
            pk.h[1] = __floats2half2_rn(r.z, r.w);
            *(uint2*)(O16 + idx) = pk.u;
        } else {
            float bn = bias[n0 + n];
            float4 e = *(const float4*)(E + (size_t)(n0 + n) * ldO + m0 + m4);
            c.x += e.x + bn; c.y += e.y + bn; c.z += e.z + bn; c.w += e.w + bn;
            *(float4*)(O32 + idx) = c;
        }
    }
}

// ---------------------------------------------------------------------------
// Host launcher
// ---------------------------------------------------------------------------
extern "C" void kernel_launch(void* const* d_in, const int* in_sizes, int n_in,
                              void* d_out, int out_size) {
    const float* x        = (const float*)d_in[0];
    const float* gn_scale = (const float*)d_in[1];
    const float* gn_bias  = (const float*)d_in[2];
    const float* qkv_w    = (const float*)d_in[3];
    const float* qkv_b    = (const float*)d_in[4];
    const float* proj_w   = (const float*)d_in[5];
    const float* proj_b   = (const float*)d_in[6];
    const float* inl_w    = (const float*)d_in[7];
    const float* inl_b    = (const float*)d_in[8];
    float* out = (float*)d_out;

    __half *hgn, *qkvT, *h1h, *h2h, *w16;
    float *h1f, *h2f, *stats;
    cudaGetSymbolAddress((void**)&hgn,   g_hgn);
    cudaGetSymbolAddress((void**)&qkvT,  g_qkvT);
    cudaGetSymbolAddress((void**)&h1f,   g_h1f);
    cudaGetSymbolAddress((void**)&h1h,   g_h1h);
    cudaGetSymbolAddress((void**)&h2f,   g_h2f);
    cudaGetSymbolAddress((void**)&h2h,   g_h2h);
    cudaGetSymbolAddress((void**)&w16,   g_w16);
    cudaGetSymbolAddress((void**)&stats, g_stats);

    const int SMMM = 132 * 128 * 4;   // 67584 (>= 2*32768)
    const int SMFL = 98304;
    cudaFuncSetAttribute(mm16_kernel<0>, cudaFuncAttributeMaxDynamicSharedMemorySize, SMMM);
    cudaFuncSetAttribute(mm16_kernel<1>, cudaFuncAttributeMaxDynamicSharedMemorySize, SMMM);
    cudaFuncSetAttribute(mm16_kernel<2>, cudaFuncAttributeMaxDynamicSharedMemorySize, SMMM);
    cudaFuncSetAttribute(flash_kernel,   cudaFuncAttributeMaxDynamicSharedMemorySize, SMFL);

    const size_t CSz = (size_t)CS;

    // 0) weights -> fp16
    f2h_kernel<<<384, 256>>>(qkv_w, w16);                    // 786432
    f2h_kernel<<<128, 256>>>(inl_w, w16 + 786432);           // 262144
    f2h_kernel<<<128, 256>>>(proj_w, w16 + 1048576);         // 262144

    // 1) GroupNorm
    gn_stats_kernel<<<B_ * NH, 256>>>(x, stats);
    gn_apply_t_kernel<<<dim3(32, 16, B_), dim3(32, 8)>>>(x, stats, gn_scale, gn_bias, hgn);

    // 2) QKV: qkvT[s,o] fp16 = qkv_w[o,:].hgn[s,:] + qkv_b[o]   (m=o, n=s)
    mm16_kernel<0><<<dim3(8, 12, B_), 256, SMMM>>>(
        w16, C_, 0,
        hgn, C_, CSz,
        nullptr, qkvT, 1536, (size_t)S_ * 1536,
        qkv_b, nullptr, 0, C_);

    // 3) fused attention -> h1 (f32 + f16)
    flash_kernel<<<dim3(8, 1, B_ * NH), 256, SMFL>>>(qkvT, h1f, h1h);

    // 4) INL x3
    const float* srcf = h1f; const __half* srch = h1h;
    float* dstf = h2f; __half* dsth = h2h;
    for (int it = 0; it < 3; it++) {
        mm16_kernel<1><<<dim3(8, 4, B_), 256, SMMM>>>(
            w16 + 786432, C_, 0,
            srch, C_, CSz,
            dstf, dsth, C_, CSz,
            inl_b, srcf, CSz, C_);
        const float* tf = srcf; srcf = dstf; dstf = (float*)tf;
        const __half* th = srch; srch = dsth; dsth = (__half*)th;
    }

    // 5) proj + residual: out[o,s] = x[o,s] + proj_w[o,:].h[s,:] + proj_b[o]
    //    (m=s, n=o, bias[n], E=x)
    mm16_kernel<2><<<dim3(4, 8, B_), 256, SMMM>>>(
        srch, C_, CSz,
        w16 + 1048576, C_, 0,
        out, nullptr, S_, CSz,
        proj_b, x, CSz, C_);
}

// round 6
// speedup vs baseline: 7.1844x; 1.5169x over previous
#include <cuda_runtime.h>
#include <cuda_fp16.h>
#include <cstdint>
#include <cstddef>

// ===========================================================================
// INLAttentionBlock, fp16 tensor-core pipeline (mma.sync m16n8k16, f32 accum):
// GN+T -> QKV -> flash(QK+softmax+PV) -> 3x INL -> proj+res
// B=8, C=512, S=1024, nh=8, hd=64. Activations token-major [b, s, c].
// MMA operands fp16; residual/Euler state kept in fp32 shadows.
// ===========================================================================

#define B_ 8
#define C_ 512
#define S_ 1024
#define NH 8
#define CS (C_ * S_)
#define CEXP 0.18033688011112042f   // 0.125 * log2(e)

__device__ __half g_hgn[(size_t)B_ * S_ * C_];        // [b, s, c] fp16
__device__ __half g_qkvT[(size_t)B_ * S_ * 1536];     // [b, s, 3C] fp16
__device__ float  g_h1f[(size_t)B_ * S_ * C_];        // fp32 shadow
__device__ __half g_h1h[(size_t)B_ * S_ * C_];
__device__ float  g_h2f[(size_t)B_ * S_ * C_];
__device__ __half g_h2h[(size_t)B_ * S_ * C_];
__device__ __half g_w16[1310720];                     // qkv|inl|proj fp16 weights
__device__ float  g_stats[2 * B_ * NH];
__device__ float2 g_part[512];

// ---------------------------------------------------------------------------
// helpers
// ---------------------------------------------------------------------------
__device__ __forceinline__ uint32_t smem_u32(const void* p) {
    uint32_t a;
    asm("{ .reg .u64 t; cvta.to.shared.u64 t, %1; cvt.u32.u64 %0, t; }" : "=r"(a) : "l"(p));
    return a;
}
__device__ __forceinline__ void ldsm4(uint32_t* r, uint32_t addr) {
    asm volatile("ldmatrix.sync.aligned.m8n8.x4.shared.b16 {%0,%1,%2,%3}, [%4];"
                 : "=r"(r[0]), "=r"(r[1]), "=r"(r[2]), "=r"(r[3]) : "r"(addr));
}
__device__ __forceinline__ void ldsm4t(uint32_t* r, uint32_t addr) {
    asm volatile("ldmatrix.sync.aligned.m8n8.x4.trans.shared.b16 {%0,%1,%2,%3}, [%4];"
                 : "=r"(r[0]), "=r"(r[1]), "=r"(r[2]), "=r"(r[3]) : "r"(addr));
}
__device__ __forceinline__ void ldsm2(uint32_t* r, uint32_t addr) {
    asm volatile("ldmatrix.sync.aligned.m8n8.x2.shared.b16 {%0,%1}, [%2];"
                 : "=r"(r[0]), "=r"(r[1]) : "r"(addr));
}
__device__ __forceinline__ void mma16(float* d, const uint32_t* a, const uint32_t* b) {
    asm volatile("mma.sync.aligned.m16n8k16.row.col.f32.f16.f16.f32 "
                 "{%0,%1,%2,%3}, {%4,%5,%6,%7}, {%8,%9}, {%0,%1,%2,%3};"
                 : "+f"(d[0]), "+f"(d[1]), "+f"(d[2]), "+f"(d[3])
                 : "r"(a[0]), "r"(a[1]), "r"(a[2]), "r"(a[3]), "r"(b[0]), "r"(b[1]));
}
#define CP16(sa, ga) asm volatile("cp.async.cg.shared.global [%0], [%1], 16;" :: "r"(sa), "l"((const void*)(ga)))
#define CPCOMMIT()   asm volatile("cp.async.commit_group;" ::: "memory")
#define CPWAIT0()    asm volatile("cp.async.wait_group 0;" ::: "memory")

// ---------------------------------------------------------------------------
// weights fp32 -> fp16, single launch (blocks 0-383 qkv, 384-511 inl, 512-639 proj)
// ---------------------------------------------------------------------------
__global__ void f2h_all_kernel(const float* __restrict__ qkv_w,
                               const float* __restrict__ inl_w,
                               const float* __restrict__ proj_w,
                               __half* __restrict__ d) {
    int bb = blockIdx.x;
    const float* s;
    int base;
    if (bb < 384)      { s = qkv_w;  base = bb * 2048; }
    else if (bb < 512) { s = inl_w;  base = (bb - 384) * 2048; d += 786432; }
    else               { s = proj_w; base = (bb - 512) * 2048; d += 1048576; }
    int i = base + threadIdx.x * 8;
    float4 a = *(const float4*)(s + i);
    float4 b = *(const float4*)(s + i + 4);
    union { __half2 h[4]; uint4 u; } pk;
    pk.h[0] = __floats2half2_rn(a.x, a.y);
    pk.h[1] = __floats2half2_rn(a.z, a.w);
    pk.h[2] = __floats2half2_rn(b.x, b.y);
    pk.h[3] = __floats2half2_rn(b.z, b.w);
    *(uint4*)(d + i) = pk.u;
}

// ---------------------------------------------------------------------------
// GroupNorm stats, two-stage (512 partial CTAs -> 1 reduce CTA)
// ---------------------------------------------------------------------------
__global__ void gn_stats_a_kernel(const float* __restrict__ x, float2* __restrict__ part) {
    __shared__ float sh[256], sh2[256];
    const int tid = threadIdx.x;
    const float4* p = (const float4*)(x + (size_t)blockIdx.x * 8192);
    float s = 0.f, s2 = 0.f;
#pragma unroll
    for (int r = 0; r < 8; r++) {
        float4 v = p[tid + r * 256];
        s  += v.x + v.y + v.z + v.w;
        s2 += v.x * v.x + v.y * v.y + v.z * v.z + v.w * v.w;
    }
    sh[tid] = s; sh2[tid] = s2;
    __syncthreads();
    for (int st = 128; st > 0; st >>= 1) {
        if (tid < st) { sh[tid] += sh[tid + st]; sh2[tid] += sh2[tid + st]; }
        __syncthreads();
    }
    if (tid == 0) part[blockIdx.x] = make_float2(sh[0], sh2[0]);
}

__global__ void gn_stats_b_kernel(const float2* __restrict__ part, float* __restrict__ stats) {
    const int t = threadIdx.x;   // 512
    float2 p = part[t];
    float s = p.x, s2 = p.y;
#pragma unroll
    for (int o = 4; o > 0; o >>= 1) {
        s  += __shfl_down_sync(0xffffffffu, s,  o, 8);
        s2 += __shfl_down_sync(0xffffffffu, s2, o, 8);
    }
    if ((t & 7) == 0) {
        int g = t >> 3;
        float mean = s * (1.f / 65536.f);
        float var  = s2 * (1.f / 65536.f) - mean * mean;
        stats[2 * g]     = mean;
        stats[2 * g + 1] = rsqrtf(var + 1e-5f);
    }
}

__global__ void gn_apply_t_kernel(const float* __restrict__ x, const float* __restrict__ stats,
                                  const float* __restrict__ sc, const float* __restrict__ bi,
                                  __half* __restrict__ hgn) {
    __shared__ float t[32][33];
    const int b = blockIdx.z;
    const int c0 = blockIdx.y * 32;
    const int s0 = blockIdx.x * 32;
    const int tx = threadIdx.x, ty = threadIdx.y;
#pragma unroll
    for (int r = 0; r < 4; r++) {
        int c = c0 + ty + r * 8;
        int bg = b * 8 + (c >> 6);
        float mean = stats[2 * bg], rstd = stats[2 * bg + 1];
        float a = rstd * sc[c];
        float bb = bi[c] - mean * a;
        t[ty + r * 8][tx] = x[(size_t)b * CS + (size_t)c * S_ + s0 + tx] * a + bb;
    }
    __syncthreads();
#pragma unroll
    for (int r = 0; r < 4; r++) {
        int s = s0 + ty + r * 8;
        hgn[(size_t)b * CS + (size_t)s * C_ + c0 + tx] = __float2half_rn(t[tx][ty + r * 8]);
    }
}

// ---------------------------------------------------------------------------
// Flash attention fp16: CTA = (b,h, 128 q rows). 256 thr / 8 warps.
// SMEM: [0,32K) warp P slices (Q staged in [0,16K) first),
//       [32K,64K) K0|V0, [64K,96K) K1|V1. K,V tiles: [t(128) x 64h] 128B rows.
// ---------------------------------------------------------------------------
__global__ void __launch_bounds__(256, 1) flash_kernel(
    const __half* __restrict__ qkvT, float* __restrict__ of, __half* __restrict__ oh)
{
    extern __shared__ char sm[];
    const uint32_t sb = smem_u32(sm);
    const int tid = threadIdx.x, wid = tid >> 5, lane = tid & 31;
    const int grp = lane >> 2, tig = lane & 3;
    const int b = blockIdx.z >> 3, h = blockIdx.z & 7;
    const int q0 = blockIdx.x * 128;
    const int wm0 = wid * 16;

    const __half* Qg = qkvT + (size_t)b * S_ * 1536 + (size_t)q0 * 1536 + h * 64;
    const __half* Kg = qkvT + (size_t)b * S_ * 1536 + 512 + h * 64;

    // cp.async per-thread offsets (tile [128 rows x 64 halves], 128B rows, SW)
    uint32_t so[4]; int go[4];
#pragma unroll
    for (int r = 0; r < 4; r++) {
        int li = tid + r * 256;
        int row = li >> 3, c8 = li & 7;
        so[r] = (uint32_t)(row * 128 + c8 * 16) ^ ((uint32_t)(row & 7) << 4);
        go[r] = row * 1536 + c8 * 8;
    }

    // prologue: Q -> [0,16K); K0/V0 -> [32K,64K)
    const uint32_t KV0 = sb + 32768;
#pragma unroll
    for (int r = 0; r < 4; r++) CP16(sb + so[r], Qg + go[r]);
#pragma unroll
    for (int r = 0; r < 4; r++) CP16(KV0 + so[r], Kg + go[r]);
#pragma unroll
    for (int r = 0; r < 4; r++) CP16(KV0 + 16384 + so[r], Kg + 512 + go[r]);
    CPCOMMIT(); CPWAIT0();
    __syncthreads();

    const int rowA = lane & 15;
    const uint32_t kxA = (uint32_t)(lane >> 4) * 16;
    const uint32_t swzA = (uint32_t)(rowA & 7) << 4;
    // x4 B-operand geometry (non-trans): rows 0-15 via lanes {0-7,16-23}+{8-15,24-31} col halves
    const int rowB4 = (lane & 7) | (((lane >> 4) & 1) << 3);
    const uint32_t kxB4 = (uint32_t)((lane >> 3) & 1) * 16;
    const uint32_t swzB4 = (uint32_t)(rowB4 & 7) << 4;

    // Q fragments: K=64 -> 4 k16 steps
    uint32_t qf[4][4];
#pragma unroll
    for (int ks = 0; ks < 4; ks++)
        ldsm4(qf[ks], sb + (uint32_t)((wm0 + rowA) * 128) + (((uint32_t)(ks * 32) + kxA) ^ swzA));
    __syncthreads();

    float m0 = -1e30f, m1 = -1e30f, l0 = 0.f, l1 = 0.f;
    float oacc[8][4];
#pragma unroll
    for (int nt = 0; nt < 8; nt++)
#pragma unroll
        for (int r = 0; r < 4; r++) oacc[nt][r] = 0.f;

    const uint32_t Pw = sb + (uint32_t)wid * 4096;   // [16 rows x 128 t] fp16, 2 panels

    for (int kv = 0; kv < 8; kv++) {
        const uint32_t Kb = sb + 32768 + (uint32_t)(kv & 1) * 32768;
        const uint32_t Vb = Kb + 16384;

        if (kv + 1 < 8) {
            const uint32_t Kn = sb + 32768 + (uint32_t)((kv + 1) & 1) * 32768;
            const __half* Kg2 = Kg + (size_t)(kv + 1) * 128 * 1536;
#pragma unroll
            for (int r = 0; r < 4; r++) CP16(Kn + so[r], Kg2 + go[r]);
#pragma unroll
            for (int r = 0; r < 4; r++) CP16(Kn + 16384 + so[r], Kg2 + 512 + go[r]);
            CPCOMMIT();
        }

        // ---- S = Q K^T  (16 x 128, k=64); K loaded as n16 pairs via ldsm4 ----
        float sacc[16][4];
#pragma unroll
        for (int nt = 0; nt < 16; nt++)
#pragma unroll
            for (int r = 0; r < 4; r++) sacc[nt][r] = 0.f;
#pragma unroll
        for (int ks = 0; ks < 4; ks++) {
#pragma unroll
            for (int np = 0; np < 8; np++) {
                uint32_t bf[4];
                ldsm4(bf, Kb + (uint32_t)((np * 16 + rowB4) * 128)
                          + (((uint32_t)(ks * 32) + kxB4) ^ swzB4));
                mma16(sacc[np * 2], qf[ks], bf);
                mma16(sacc[np * 2 + 1], qf[ks], bf + 2);
            }
        }

        // ---- online softmax ----
        float r0 = -1e30f, r1 = -1e30f;
#pragma unroll
        for (int nt = 0; nt < 16; nt++) {
            r0 = fmaxf(r0, fmaxf(sacc[nt][0], sacc[nt][1]));
            r1 = fmaxf(r1, fmaxf(sacc[nt][2], sacc[nt][3]));
        }
        r0 = fmaxf(r0, __shfl_xor_sync(0xffffffffu, r0, 1));
        r0 = fmaxf(r0, __shfl_xor_sync(0xffffffffu, r0, 2));
        r1 = fmaxf(r1, __shfl_xor_sync(0xffffffffu, r1, 1));
        r1 = fmaxf(r1, __shfl_xor_sync(0xffffffffu, r1, 2));
        float mn0 = fmaxf(m0, r0), mn1 = fmaxf(m1, r1);
        float a0 = exp2f((m0 - mn0) * CEXP);
        float a1 = exp2f((m1 - mn1) * CEXP);
        m0 = mn0; m1 = mn1;
        l0 *= a0; l1 *= a1;
#pragma unroll
        for (int nt = 0; nt < 8; nt++) {
            oacc[nt][0] *= a0; oacc[nt][1] *= a0;
            oacc[nt][2] *= a1; oacc[nt][3] *= a1;
        }
#pragma unroll
        for (int nt = 0; nt < 16; nt++) {
            float p0 = exp2f((sacc[nt][0] - m0) * CEXP);
            float p1 = exp2f((sacc[nt][1] - m0) * CEXP);
            float p2 = exp2f((sacc[nt][2] - m1) * CEXP);
            float p3 = exp2f((sacc[nt][3] - m1) * CEXP);
            l0 += p0 + p1; l1 += p2 + p3;
            int t = nt * 8 + tig * 2;
            uint32_t off = (Pw - sb) + (uint32_t)(t >> 6) * 2048 + (uint32_t)(grp * 128)
                           + (((uint32_t)(t & 63) * 2) ^ ((uint32_t)grp << 4));
            *(__half2*)(sm + off)        = __floats2half2_rn(p0, p1);
            *(__half2*)(sm + off + 1024) = __floats2half2_rn(p2, p3);  // row grp+8
        }
        __syncwarp();

        // ---- O += P V  (16 x 64, k=128; V via ldsm4.trans over n16 pairs) ----
#pragma unroll
        for (int kt = 0; kt < 8; kt++) {
            uint32_t pf[4];
            ldsm4(pf, Pw + (uint32_t)(kt >> 2) * 2048 + (uint32_t)(rowA * 128)
                      + (((uint32_t)((kt & 3) * 32) + kxA) ^ swzA));
#pragma unroll
            for (int np = 0; np < 4; np++) {
                uint32_t bf[4];
                ldsm4t(bf, Vb + (uint32_t)((kt * 16 + rowA) * 128)
                           + (((uint32_t)(np * 32) + ((uint32_t)(lane >> 4) * 16)) ^ swzA));
                mma16(oacc[np * 2], pf, bf);
                mma16(oacc[np * 2 + 1], pf, bf + 2);
            }
        }

        if (kv + 1 < 8) CPWAIT0();
        __syncthreads();
    }

    // ---- finalize ----
    l0 += __shfl_xor_sync(0xffffffffu, l0, 1);
    l0 += __shfl_xor_sync(0xffffffffu, l0, 2);
    l1 += __shfl_xor_sync(0xffffffffu, l1, 1);
    l1 += __shfl_xor_sync(0xffffffffu, l1, 2);
    float i0 = 1.f / l0, i1 = 1.f / l1;
    const int sg = q0 + wm0 + grp;
    size_t ob = (size_t)b * CS + (size_t)sg * 512 + h * 64 + tig * 2;
#pragma unroll
    for (int nt = 0; nt < 8; nt++) {
        float x0 = oacc[nt][0] * i0, x1 = oacc[nt][1] * i0;
        float x2 = oacc[nt][2] * i1, x3 = oacc[nt][3] * i1;
        *(float2*)(of + ob + nt * 8)            = make_float2(x0, x1);
        *(float2*)(of + ob + 8 * 512 + nt * 8)  = make_float2(x2, x3);
        *(__half2*)(oh + ob + nt * 8)           = __floats2half2_rn(x0, x1);
        *(__half2*)(oh + ob + 8 * 512 + nt * 8) = __floats2half2_rn(x2, x3);
    }
}

// ---------------------------------------------------------------------------
// fp16 GEMM: D[m,n] = epi( sum_k A[m,k]*B[n,k] ), A/B fp16 K-contig.
// BM=128, BN=128, BK=64. EPI: 0 QKV(out fp16, +bias[m]);
// 1 INL(out f32+f16, E + 0.1*tanh(v+bias[m])); 2 proj(out f32, E + v + bias[n]).
// ---------------------------------------------------------------------------
template <int EPI>
__global__ void __launch_bounds__(256) mm16_kernel(
    const __half* __restrict__ Abase, int ldA, size_t sAo,
    const __half* __restrict__ Bbase, int ldB, size_t sBo,
    float* __restrict__ O32, __half* __restrict__ O16, int ldO, size_t sOo,
    const float* __restrict__ bias,
    const float* __restrict__ Ebase, size_t sEo,
    int K)
{
    constexpr int ABYTES = 16384;       // 128 x 64 halves
    constexpr int STAGE  = 32768;
    constexpr int PITCH  = 132;

    extern __shared__ char smemc[];
    const uint32_t sb = smem_u32(smemc);
    const int tid = threadIdx.x;
    const int wid = tid >> 5;
    const int lane = tid & 31;
    const int grp = lane >> 2, tig = lane & 3;

    const int z = blockIdx.z;
    const __half* Ag = Abase + (size_t)z * sAo;
    const __half* Bg = Bbase + (size_t)z * sBo;
    const float*  E  = (EPI != 0) ? (Ebase + (size_t)z * sEo) : nullptr;

    const int m0 = blockIdx.y * 128;
    const int n0 = blockIdx.x * 128;
    const int wm0 = (wid & 1) * 64;
    const int wn0 = (wid >> 1) * 32;

    uint32_t asw[4];
    size_t ago[4], bgo[4];
#pragma unroll
    for (int r = 0; r < 4; r++) {
        int li = tid + r * 256;
        int row = li >> 3, c8 = li & 7;
        asw[r] = (uint32_t)(row * 128 + c8 * 16) ^ ((uint32_t)(row & 7) << 4);
        ago[r] = (size_t)(m0 + row) * ldA + c8 * 8;
        bgo[r] = (size_t)(n0 + row) * ldB + c8 * 8;
    }

    const int rowA = lane & 15;
    const uint32_t kxA = (uint32_t)(lane >> 4) * 16;
    const uint32_t swzA = (uint32_t)(rowA & 7) << 4;
    const int rowB4 = (lane & 7) | (((lane >> 4) & 1) << 3);
    const uint32_t kxB4 = (uint32_t)((lane >> 3) & 1) * 16;
    const uint32_t swzB4 = (uint32_t)(rowB4 & 7) << 4;

    float acc[4][4][4];
#pragma unroll
    for (int mt = 0; mt < 4; mt++)
#pragma unroll
        for (int nt = 0; nt < 4; nt++)
#pragma unroll
            for (int r = 0; r < 4; r++) acc[mt][nt][r] = 0.f;

    const int nkt = K >> 6;

    // prologue: tile 0
#pragma unroll
    for (int r = 0; r < 4; r++) { CP16(sb + asw[r], Ag + ago[r]); CP16(sb + ABYTES + asw[r], Bg + bgo[r]); }
    CPCOMMIT(); CPWAIT0();
    __syncthreads();

    for (int kt = 0; kt < nkt; kt++) {
        const int cur = kt & 1;
        const uint32_t As = sb + cur * STAGE;
        const uint32_t Bs = As + ABYTES;

        if (kt + 1 < nkt) {
            const uint32_t nb = sb + (cur ^ 1) * STAGE;
            const int k0 = (kt + 1) << 6;
#pragma unroll
            for (int r = 0; r < 4; r++) { CP16(nb + asw[r], Ag + ago[r] + k0); CP16(nb + ABYTES + asw[r], Bg + bgo[r] + k0); }
            CPCOMMIT();
        }

#pragma unroll
        for (int ks = 0; ks < 4; ks++) {
            uint32_t afr[4][4];
#pragma unroll
            for (int mt = 0; mt < 4; mt++)
                ldsm4(afr[mt], As + (uint32_t)((wm0 + mt * 16 + rowA) * 128)
                              + (((uint32_t)(ks * 32) + kxA) ^ swzA));
            uint32_t bfr[2][4];
#pragma unroll
            for (int np = 0; np < 2; np++)
                ldsm4(bfr[np], Bs + (uint32_t)((wn0 + np * 16 + rowB4) * 128)
                              + (((uint32_t)(ks * 32) + kxB4) ^ swzB4));
#pragma unroll
            for (int mt = 0; mt < 4; mt++)
#pragma unroll
                for (int np = 0; np < 2; np++) {
                    mma16(acc[mt][np * 2], afr[mt], bfr[np]);
                    mma16(acc[mt][np * 2 + 1], afr[mt], bfr[np] + 2);
                }
        }

        if (kt + 1 < nkt) { CPWAIT0(); __syncthreads(); }
    }

    // ---- epilogue: transpose through SMEM ([n][m] fp32) ----
    __syncthreads();
    float* Csm = (float*)smemc;
#pragma unroll
    for (int mt = 0; mt < 4; mt++) {
#pragma unroll
        for (int nt = 0; nt < 4; nt++) {
            int m = wm0 + mt * 16 + grp;
            int n = wn0 + nt * 8 + tig * 2;
            Csm[(n)     * PITCH + m]     = acc[mt][nt][0];
            Csm[(n + 1) * PITCH + m]     = acc[mt][nt][1];
            Csm[(n)     * PITCH + m + 8] = acc[mt][nt][2];
            Csm[(n + 1) * PITCH + m + 8] = acc[mt][nt][3];
        }
    }
    __syncthreads();

#pragma unroll
    for (int it = 0; it < 16; it++) {
        int li = tid + it * 256;
        int n = li >> 5, m4 = (li & 31) << 2;
        float4 c = *(float4*)(Csm + n * PITCH + m4);
        size_t idx = (size_t)z * sOo + (size_t)(n0 + n) * ldO + m0 + m4;
        if (EPI == 0) {
            float4 bm = *(const float4*)(bias + m0 + m4);
            union { __half2 h[2]; uint2 u; } pk;
            pk.h[0] = __floats2half2_rn(c.x + bm.x, c.y + bm.y);
            pk.h[1] = __floats2half2_rn(c.z + bm.z, c.w + bm.w);
            *(uint2*)(O16 + idx) = pk.u;
        } else if (EPI == 1) {
            float4 bm = *(const float4*)(bias + m0 + m4);
            float4 e = *(const float4*)(E + (size_t)(n0 + n) * ldO + m0 + m4);
            float4 r;
            r.x = e.x + 0.1f * tanhf(c.x + bm.x);
            r.y = e.y + 0.1f * tanhf(c.y + bm.y);
            r.z = e.z + 0.1f * tanhf(c.z + bm.z);
            r.w = e.w + 0.1f * tanhf(c.w + bm.w);
            *(float4*)(O32 + idx) = r;
            union { __half2 h[2]; uint2 u; } pk;
            pk.h[0] = __floats2half2_rn(r.x, r.y);
            pk.h[1] = __floats2half2_rn(r.z, r.w);
            *(uint2*)(O16 + idx) = pk.u;
        } else {
            float bn = bias[n0 + n];
            float4 e = *(const float4*)(E + (size_t)(n0 + n) * ldO + m0 + m4);
            c.x += e.x + bn; c.y += e.y + bn; c.z += e.z + bn; c.w += e.w + bn;
            *(float4*)(O32 + idx) = c;
        }
    }
}

// ---------------------------------------------------------------------------
// Host launcher
// ---------------------------------------------------------------------------
extern "C" void kernel_launch(void* const* d_in, const int* in_sizes, int n_in,
                              void* d_out, int out_size) {
    const float* x        = (const float*)d_in[0];
    const float* gn_scale = (const float*)d_in[1];
    const float* gn_bias  = (const float*)d_in[2];
    const float* qkv_w    = (const float*)d_in[3];
    const float* qkv_b    = (const float*)d_in[4];
    const float* proj_w   = (const float*)d_in[5];
    const float* proj_b   = (const float*)d_in[6];
    const float* inl_w    = (const float*)d_in[7];
    const float* inl_b    = (const float*)d_in[8];
    float* out = (float*)d_out;

    __half *hgn, *qkvT, *h1h, *h2h, *w16;
    float *h1f, *h2f, *stats;
    float2* part;
    cudaGetSymbolAddress((void**)&hgn,   g_hgn);
    cudaGetSymbolAddress((void**)&qkvT,  g_qkvT);
    cudaGetSymbolAddress((void**)&h1f,   g_h1f);
    cudaGetSymbolAddress((void**)&h1h,   g_h1h);
    cudaGetSymbolAddress((void**)&h2f,   g_h2f);
    cudaGetSymbolAddress((void**)&h2h,   g_h2h);
    cudaGetSymbolAddress((void**)&w16,   g_w16);
    cudaGetSymbolAddress((void**)&stats, g_stats);
    cudaGetSymbolAddress((void**)&part,  g_part);

    const int SMMM = 132 * 128 * 4;   // 67584 (>= 2*32768)
    const int SMFL = 98304;
    cudaFuncSetAttribute(mm16_kernel<0>, cudaFuncAttributeMaxDynamicSharedMemorySize, SMMM);
    cudaFuncSetAttribute(mm16_kernel<1>, cudaFuncAttributeMaxDynamicSharedMemorySize, SMMM);
    cudaFuncSetAttribute(mm16_kernel<2>, cudaFuncAttributeMaxDynamicSharedMemorySize, SMMM);
    cudaFuncSetAttribute(flash_kernel,   cudaFuncAttributeMaxDynamicSharedMemorySize, SMFL);

    const size_t CSz = (size_t)CS;

    // 0) weights -> fp16 (single launch)
    f2h_all_kernel<<<640, 256>>>(qkv_w, inl_w, proj_w, w16);

    // 1) GroupNorm (two-stage stats + apply/transpose)
    gn_stats_a_kernel<<<512, 256>>>(x, part);
    gn_stats_b_kernel<<<1, 512>>>(part, stats);
    gn_apply_t_kernel<<<dim3(32, 16, B_), dim3(32, 8)>>>(x, stats, gn_scale, gn_bias, hgn);

    // 2) QKV: qkvT[s,o] fp16 = qkv_w[o,:].hgn[s,:] + qkv_b[o]   (m=o, n=s)
    mm16_kernel<0><<<dim3(8, 12, B_), 256, SMMM>>>(
        w16, C_, 0,
        hgn, C_, CSz,
        nullptr, qkvT, 1536, (size_t)S_ * 1536,
        qkv_b, nullptr, 0, C_);

    // 3) fused attention -> h1 (f32 + f16)
    flash_kernel<<<dim3(8, 1, B_ * NH), 256, SMFL>>>(qkvT, h1f, h1h);

    // 4) INL x3
    const float* srcf = h1f; const __half* srch = h1h;
    float* dstf = h2f; __half* dsth = h2h;
    for (int it = 0; it < 3; it++) {
        mm16_kernel<1><<<dim3(8, 4, B_), 256, SMMM>>>(
            w16 + 786432, C_, 0,
            srch, C_, CSz,
            dstf, dsth, C_, CSz,
            inl_b, srcf, CSz, C_);
        const float* tf = srcf; srcf = dstf; dstf = (float*)tf;
        const __half* th = srch; srch = dsth; dsth = (__half*)th;
    }

    // 5) proj + residual: out[o,s] = x[o,s] + proj_w[o,:].h[s,:] + proj_b[o]
    //    (m=s, n=o, bias[n], E=x)
    mm16_kernel<2><<<dim3(4, 8, B_), 256, SMMM>>>(
        srch, C_, CSz,
        w16 + 1048576, C_, 0,
        out, nullptr, S_, CSz,
        proj_b, x, CSz, C_);
}